// round 12
// baseline (speedup 1.0000x reference)
#include <cuda_runtime.h>
#include <cuda_bf16.h>
#include <cuda.h>
#include <dlfcn.h>
#include <cstdint>

#define D_MODEL 1024
#define HIDDEN  2048
#define D_STATE 16
#define BATCH   2
#define SEQ     2048
#define MTOK    4096
#define NCHK    32
#define CHK     64

// ---------------- GEMM tiling -------------------------------------------------
#define BM 128
#define BN 128
#define BKE 64
#define RB 128
#define TILE_B (128 * 128)
#define UG_STAGE (5 * TILE_B)                 // Ahi,Alo,Xhi,Xlo,Ghi
#define SMEM_UG (2 * UG_STAGE + 1024)         // 164864
#define SMEM_OUT (3 * 4 * TILE_B + 1024)      // 197632 (3-stage, 4 tiles)
#define SMEM_DT (3 * 2 * TILE_B + 1024)       // 99328  (3-stage, 2 tiles, 2 CTA/SM)

// ---------------- scratch ----------------------------------------------------
__device__ float g_u[(size_t)MTOK * HIDDEN];
__device__ float g_g[(size_t)MTOK * HIDDEN];
__device__ float g_outp[(size_t)MTOK * D_MODEL];
__device__ float g_dtpart[(MTOK / BM) * HIDDEN];
__device__ float g_Ad[HIDDEN * D_STATE];
__device__ float g_Bd[HIDDEN * D_STATE];
__device__ float g_state[(size_t)BATCH * NCHK * HIDDEN * D_STATE];
__device__ float g_init[(size_t)BATCH * NCHK * HIDDEN * D_STATE];

__device__ __nv_bfloat16 g_xhi[(size_t)MTOK * D_MODEL];
__device__ __nv_bfloat16 g_xlo[(size_t)MTOK * D_MODEL];
__device__ __nv_bfloat16 g_wxhi[HIDDEN * D_MODEL];
__device__ __nv_bfloat16 g_wxlo[HIDDEN * D_MODEL];
__device__ __nv_bfloat16 g_wghi[HIDDEN * D_MODEL];
__device__ __nv_bfloat16 g_wdthi[HIDDEN * D_MODEL];
__device__ __nv_bfloat16 g_wohi[D_MODEL * HIDDEN];
__device__ __nv_bfloat16 g_wolo[D_MODEL * HIDDEN];
__device__ __nv_bfloat16 g_yhi[(size_t)MTOK * HIDDEN];
__device__ __nv_bfloat16 g_ylo[(size_t)MTOK * HIDDEN];

// ---------------- helpers ----------------------------------------------------
__device__ __forceinline__ float softplusf(float x) {
    return fmaxf(x, 0.f) + log1pf(expf(-fabsf(x)));
}
__device__ __forceinline__ float sigmoidf_(float x) {
    return 1.f / (1.f + expf(-x));
}
__device__ __forceinline__ uint32_t smem_u32(const void* p) {
    uint32_t a;
    asm("{ .reg .u64 t; cvta.to.shared.u64 t, %1; cvt.u32.u64 %0, t; }"
        : "=r"(a) : "l"(p));
    return a;
}
__device__ __forceinline__ void ldm_x4(uint32_t* r, uint32_t addr) {
    asm volatile("ldmatrix.sync.aligned.m8n8.x4.shared.b16 {%0,%1,%2,%3}, [%4];"
                 : "=r"(r[0]), "=r"(r[1]), "=r"(r[2]), "=r"(r[3]) : "r"(addr));
}
__device__ __forceinline__ void mma_bf16(float* d, const uint32_t* a,
                                         const uint32_t* b) {
    asm volatile(
        "mma.sync.aligned.m16n8k16.row.col.f32.bf16.bf16.f32 "
        "{%0,%1,%2,%3}, {%4,%5,%6,%7}, {%8,%9}, {%0,%1,%2,%3};"
        : "+f"(d[0]), "+f"(d[1]), "+f"(d[2]), "+f"(d[3])
        : "r"(a[0]), "r"(a[1]), "r"(a[2]), "r"(a[3]), "r"(b[0]), "r"(b[1]));
}
__device__ __forceinline__ void mbar_init(uint32_t addr) {
    asm volatile("mbarrier.init.shared.b64 [%0], 1;" :: "r"(addr) : "memory");
}
__device__ __forceinline__ void mbar_expect(uint32_t addr, uint32_t bytes) {
    asm volatile("mbarrier.arrive.expect_tx.shared.b64 _, [%0], %1;"
                 :: "r"(addr), "r"(bytes) : "memory");
}
__device__ __forceinline__ void mbar_wait(uint32_t addr, uint32_t parity) {
    asm volatile(
        "{\n\t.reg .pred P;\n\t"
        "W_%=:\n\t"
        "mbarrier.try_wait.parity.acquire.cta.shared::cta.b64 P, [%0], %1, 0x989680;\n\t"
        "@P bra D_%=;\n\t"
        "bra W_%=;\n\t"
        "D_%=:\n\t}"
        :: "r"(addr), "r"(parity) : "memory");
}
__device__ __forceinline__ void tma2d(uint32_t smaddr, const CUtensorMap* m,
                                      int cx, int cy, uint32_t mbar) {
    asm volatile(
        "cp.async.bulk.tensor.2d.shared::cta.global.tile.mbarrier::complete_tx::bytes "
        "[%0], [%1, {%2, %3}], [%4];"
        :: "r"(smaddr), "l"(m), "r"(cx), "r"(cy), "r"(mbar) : "memory");
}

// ---------------- fp32 -> bf16 hi/lo split (x) --------------------------------
__global__ __launch_bounds__(256) void split_kernel(
    const float4* __restrict__ src, __nv_bfloat162* __restrict__ hi,
    __nv_bfloat162* __restrict__ lo, int n4)
{
    int i = blockIdx.x * blockDim.x + threadIdx.x;
    if (i >= n4) return;
    float4 v = src[i];
    __nv_bfloat16 h0 = __float2bfloat16(v.x);
    __nv_bfloat16 h1 = __float2bfloat16(v.y);
    __nv_bfloat16 h2 = __float2bfloat16(v.z);
    __nv_bfloat16 h3 = __float2bfloat16(v.w);
    hi[i * 2 + 0] = __nv_bfloat162(h0, h1);
    hi[i * 2 + 1] = __nv_bfloat162(h2, h3);
    if (lo) {
        __nv_bfloat16 l0 = __float2bfloat16(v.x - __bfloat162float(h0));
        __nv_bfloat16 l1 = __float2bfloat16(v.y - __bfloat162float(h1));
        __nv_bfloat16 l2 = __float2bfloat16(v.z - __bfloat162float(h2));
        __nv_bfloat16 l3 = __float2bfloat16(v.w - __bfloat162float(h3));
        lo[i * 2 + 0] = __nv_bfloat162(l0, l1);
        lo[i * 2 + 1] = __nv_bfloat162(l2, l3);
    }
}

// ---------------- fused weight split ------------------------------------------
#define WN4 (HIDDEN * D_MODEL / 4)   // 524288 = 2^19
__global__ __launch_bounds__(256) void split_w_kernel(
    const float4* __restrict__ wx, const float4* __restrict__ wg,
    const float4* __restrict__ wdt, const float4* __restrict__ wo)
{
    int gi = blockIdx.x * blockDim.x + threadIdx.x;
    int arr = gi >> 19;
    int i = gi & (WN4 - 1);
    const float4* src = (arr == 0) ? wx : (arr == 1) ? wg : (arr == 2) ? wdt : wo;
    __nv_bfloat162* hi = (arr == 0) ? (__nv_bfloat162*)g_wxhi
                       : (arr == 1) ? (__nv_bfloat162*)g_wghi
                       : (arr == 2) ? (__nv_bfloat162*)g_wdthi
                                    : (__nv_bfloat162*)g_wohi;
    __nv_bfloat162* lo = (arr == 0) ? (__nv_bfloat162*)g_wxlo
                       : (arr == 3) ? (__nv_bfloat162*)g_wolo : nullptr;
    float4 v = src[i];
    __nv_bfloat16 h0 = __float2bfloat16(v.x);
    __nv_bfloat16 h1 = __float2bfloat16(v.y);
    __nv_bfloat16 h2 = __float2bfloat16(v.z);
    __nv_bfloat16 h3 = __float2bfloat16(v.w);
    hi[i * 2 + 0] = __nv_bfloat162(h0, h1);
    hi[i * 2 + 1] = __nv_bfloat162(h2, h3);
    if (lo) {
        __nv_bfloat16 l0 = __float2bfloat16(v.x - __bfloat162float(h0));
        __nv_bfloat16 l1 = __float2bfloat16(v.y - __bfloat162float(h1));
        __nv_bfloat16 l2 = __float2bfloat16(v.z - __bfloat162float(h2));
        __nv_bfloat16 l3 = __float2bfloat16(v.w - __bfloat162float(h3));
        lo[i * 2 + 0] = __nv_bfloat162(l0, l1);
        lo[i * 2 + 1] = __nv_bfloat162(l2, l3);
    }
}

// ---------------- fused u + gate GEMM (TMA, 2-stage, 5 tiles, 128x128) --------
__global__ __launch_bounds__(256, 1) void gemm_ug_tma(
    const __grid_constant__ CUtensorMap mAh, const __grid_constant__ CUtensorMap mAl,
    const __grid_constant__ CUtensorMap mXh, const __grid_constant__ CUtensorMap mXl,
    const __grid_constant__ CUtensorMap mGh,
    const float* __restrict__ bx, const float* __restrict__ bg,
    float* __restrict__ Cu, float* __restrict__ Cg)
{
    const int N = HIDDEN;
    extern __shared__ char smraw[];
    uint32_t sb = (smem_u32(smraw) + 1023u) & ~1023u;
    __shared__ uint64_t mbarS[2];
    uint32_t mb = smem_u32(mbarS);

    const int tid = threadIdx.x;
    const int wid = tid >> 5, lane = tid & 31;
    const int wm = wid & 1, wn = wid >> 1;
    const int am0 = blockIdx.y * BM;
    const int bn0 = blockIdx.x * BN;

    if (tid == 0) { mbar_init(mb); mbar_init(mb + 8); }
    __syncthreads();

    auto issue = [&](int s) {
        if (tid != 0) return;
        uint32_t bar = mb + (uint32_t)(s & 1) * 8;
        mbar_expect(bar, UG_STAGE);
        uint32_t st = sb + (uint32_t)(s & 1) * UG_STAGE;
        int kc = s * BKE;
        tma2d(st + 0 * TILE_B, &mAh, kc, am0, bar);
        tma2d(st + 1 * TILE_B, &mAl, kc, am0, bar);
        tma2d(st + 2 * TILE_B, &mXh, kc, bn0, bar);
        tma2d(st + 3 * TILE_B, &mXl, kc, bn0, bar);
        tma2d(st + 4 * TILE_B, &mGh, kc, bn0, bar);
    };
    issue(0); issue(1);

    float acc_u[4][4][4], acc_g[4][4][4];
#pragma unroll
    for (int i = 0; i < 4; i++)
#pragma unroll
        for (int j = 0; j < 4; j++)
#pragma unroll
            for (int v = 0; v < 4; v++) { acc_u[i][j][v] = 0.f; acc_g[i][j][v] = 0.f; }

    const int arA = wm * 64 + (lane & 15);
    const int ahalf = lane >> 4;
    const uint32_t axor = (uint32_t)(arA & 7);
    uint32_t aoff[4];
#pragma unroll
    for (int mf = 0; mf < 4; mf++) aoff[mf] = (uint32_t)(arA + mf * 16) * RB;

    const int nrB = wn * 32 + (lane & 7) + ((lane >> 4) << 3);
    const int khalf = (lane >> 3) & 1;
    const uint32_t bxor = (uint32_t)(nrB & 7);
    uint32_t boff[2];
#pragma unroll
    for (int nf = 0; nf < 2; nf++) boff[nf] = (uint32_t)(nrB + nf * 16) * RB;

    const int NCH = D_MODEL / BKE;   // 16
    for (int ch = 0; ch < NCH; ch++) {
        mbar_wait(mb + (uint32_t)(ch & 1) * 8, (uint32_t)((ch >> 1) & 1));
        const uint32_t st = sb + (uint32_t)(ch & 1) * UG_STAGE;

#pragma unroll
        for (int ks = 0; ks < 4; ks++) {
            const uint32_t asg = (((uint32_t)(ks * 2 + ahalf)) ^ axor) << 4;
            const uint32_t bsg = (((uint32_t)(ks * 2 + khalf)) ^ bxor) << 4;
            uint32_t ah[4][4], al[4][4];
#pragma unroll
            for (int mf = 0; mf < 4; mf++) {
                ldm_x4(ah[mf], st + 0 * TILE_B + aoff[mf] + asg);
                ldm_x4(al[mf], st + 1 * TILE_B + aoff[mf] + asg);
            }
            {
                uint32_t bh[4][2], bl[4][2];
#pragma unroll
                for (int nf = 0; nf < 2; nf++) {
                    uint32_t rr[4];
                    ldm_x4(rr, st + 2 * TILE_B + boff[nf] + bsg);
                    bh[nf * 2 + 0][0] = rr[0]; bh[nf * 2 + 0][1] = rr[1];
                    bh[nf * 2 + 1][0] = rr[2]; bh[nf * 2 + 1][1] = rr[3];
                    ldm_x4(rr, st + 3 * TILE_B + boff[nf] + bsg);
                    bl[nf * 2 + 0][0] = rr[0]; bl[nf * 2 + 0][1] = rr[1];
                    bl[nf * 2 + 1][0] = rr[2]; bl[nf * 2 + 1][1] = rr[3];
                }
#pragma unroll
                for (int mf = 0; mf < 4; mf++)
#pragma unroll
                    for (int nfi = 0; nfi < 4; nfi++) {
                        mma_bf16(acc_u[mf][nfi], ah[mf], bh[nfi]);
                        mma_bf16(acc_u[mf][nfi], ah[mf], bl[nfi]);
                        mma_bf16(acc_u[mf][nfi], al[mf], bh[nfi]);
                    }
            }
            {
                uint32_t gh[4][2];
#pragma unroll
                for (int nf = 0; nf < 2; nf++) {
                    uint32_t rr[4];
                    ldm_x4(rr, st + 4 * TILE_B + boff[nf] + bsg);
                    gh[nf * 2 + 0][0] = rr[0]; gh[nf * 2 + 0][1] = rr[1];
                    gh[nf * 2 + 1][0] = rr[2]; gh[nf * 2 + 1][1] = rr[3];
                }
#pragma unroll
                for (int mf = 0; mf < 4; mf++)
#pragma unroll
                    for (int nfi = 0; nfi < 4; nfi++) {
                        mma_bf16(acc_g[mf][nfi], ah[mf], gh[nfi]);
                        mma_bf16(acc_g[mf][nfi], al[mf], gh[nfi]);
                    }
            }
        }
        __syncthreads();
        if (ch + 2 < NCH) issue(ch + 2);
    }

#pragma unroll
    for (int mf = 0; mf < 4; mf++) {
        const int r0 = am0 + wm * 64 + mf * 16 + (lane >> 2);
#pragma unroll
        for (int h = 0; h < 2; h++) {
            const int row = r0 + h * 8;
#pragma unroll
            for (int nfi = 0; nfi < 4; nfi++) {
                const int col = bn0 + wn * 32 + nfi * 8 + (lane & 3) * 2;
                float u0 = acc_u[mf][nfi][h * 2 + 0] + bx[col];
                float u1 = acc_u[mf][nfi][h * 2 + 1] + bx[col + 1];
                float g0 = sigmoidf_(acc_g[mf][nfi][h * 2 + 0] + bg[col]);
                float g1 = sigmoidf_(acc_g[mf][nfi][h * 2 + 1] + bg[col + 1]);
                *(float2*)&Cu[(size_t)row * N + col] = make_float2(u0, u1);
                *(float2*)&Cg[(size_t)row * N + col] = make_float2(g0, g1);
            }
        }
    }
}

// ---------------- dt GEMM: 1-term, NS=3, 2 CTAs/SM ----------------------------
__global__ __launch_bounds__(256, 2) void gemm_dt(
    const __grid_constant__ CUtensorMap mAh, const __grid_constant__ CUtensorMap mBh,
    const float* __restrict__ bias, float* __restrict__ colsum)
{
    constexpr int NS = 3;
    constexpr uint32_t STAGE = 2 * TILE_B;
    constexpr uint32_t BHOFF = TILE_B;
    const int N = HIDDEN, K = D_MODEL;

    extern __shared__ char smraw[];
    uint32_t sb = (smem_u32(smraw) + 1023u) & ~1023u;
    __shared__ uint64_t mbarS[NS];
    uint32_t mb = smem_u32(mbarS);

    const int tid = threadIdx.x;
    const int wid = tid >> 5, lane = tid & 31;
    const int wm = wid & 1, wn = wid >> 1;
    const int am0 = blockIdx.y * BM;
    const int bn0 = blockIdx.x * BN;

    if (tid == 0) {
#pragma unroll
        for (int s = 0; s < NS; s++) mbar_init(mb + s * 8);
    }
    __syncthreads();

    auto issue = [&](int s) {
        if (tid != 0) return;
        int slot = s % NS;
        uint32_t bar = mb + (uint32_t)slot * 8;
        mbar_expect(bar, STAGE);
        uint32_t st = sb + (uint32_t)slot * STAGE;
        int kc = s * BKE;
        tma2d(st, &mAh, kc, am0, bar);
        tma2d(st + BHOFF, &mBh, kc, bn0, bar);
    };
    const int NCH = K / BKE;
#pragma unroll
    for (int s = 0; s < NS; s++) if (s < NCH) issue(s);

    float acc[4][4][4];
#pragma unroll
    for (int i = 0; i < 4; i++)
#pragma unroll
        for (int j = 0; j < 4; j++)
#pragma unroll
            for (int v = 0; v < 4; v++) acc[i][j][v] = 0.f;

    const int arA = wm * 64 + (lane & 15);
    const int ahalf = lane >> 4;
    const uint32_t axor = (uint32_t)(arA & 7);
    uint32_t aoff[4];
#pragma unroll
    for (int mf = 0; mf < 4; mf++) aoff[mf] = (uint32_t)(arA + mf * 16) * RB;

    const int nrB = wn * 32 + (lane & 7) + ((lane >> 4) << 3);
    const int khalf = (lane >> 3) & 1;
    const uint32_t bxor = (uint32_t)(nrB & 7);
    uint32_t boff[2];
#pragma unroll
    for (int nf = 0; nf < 2; nf++) boff[nf] = (uint32_t)(nrB + nf * 16) * RB;

    for (int ch = 0; ch < NCH; ch++) {
        int slot = ch % NS;
        mbar_wait(mb + (uint32_t)slot * 8, (uint32_t)((ch / NS) & 1));
        const uint32_t st = sb + (uint32_t)slot * STAGE;

#pragma unroll
        for (int ks = 0; ks < 4; ks++) {
            uint32_t a[4][4], bh[4][2];
            const uint32_t asg = (((uint32_t)(ks * 2 + ahalf)) ^ axor) << 4;
            const uint32_t bsg = (((uint32_t)(ks * 2 + khalf)) ^ bxor) << 4;
#pragma unroll
            for (int nf = 0; nf < 2; nf++) {
                uint32_t rr[4];
                ldm_x4(rr, st + BHOFF + boff[nf] + bsg);
                bh[nf * 2 + 0][0] = rr[0]; bh[nf * 2 + 0][1] = rr[1];
                bh[nf * 2 + 1][0] = rr[2]; bh[nf * 2 + 1][1] = rr[3];
            }
#pragma unroll
            for (int mf = 0; mf < 4; mf++) ldm_x4(a[mf], st + aoff[mf] + asg);
#pragma unroll
            for (int mf = 0; mf < 4; mf++)
#pragma unroll
                for (int nfi = 0; nfi < 4; nfi++)
                    mma_bf16(acc[mf][nfi], a[mf], bh[nfi]);
        }
        __syncthreads();
        if (ch + NS < NCH) issue(ch + NS);
    }

    float* red = (float*)smraw;
#pragma unroll
    for (int nfi = 0; nfi < 4; nfi++) {
        const int colb = bn0 + wn * 32 + nfi * 8 + (lane & 3) * 2;
        const float b0 = bias[colb], b1 = bias[colb + 1];
        float s0 = 0.f, s1 = 0.f;
#pragma unroll
        for (int mf = 0; mf < 4; mf++) {
            s0 += softplusf(acc[mf][nfi][0] + b0);
            s1 += softplusf(acc[mf][nfi][1] + b1);
            s0 += softplusf(acc[mf][nfi][2] + b0);
            s1 += softplusf(acc[mf][nfi][3] + b1);
        }
#pragma unroll
        for (int o = 4; o <= 16; o <<= 1) {
            s0 += __shfl_xor_sync(0xffffffffu, s0, o);
            s1 += __shfl_xor_sync(0xffffffffu, s1, o);
        }
        if (lane < 4) {
            int c = wn * 32 + nfi * 8 + lane * 2;
            red[wm * 128 + c] = s0;
            red[wm * 128 + c + 1] = s1;
        }
    }
    __syncthreads();
    if (tid < 128)
        colsum[(size_t)blockIdx.y * N + bn0 + tid] = red[tid] + red[128 + tid];
}

// ---------------- out GEMM: 3-term, NS=3, ks-pipelined fragments (128x128) ----
__global__ __launch_bounds__(256, 1) void gemm_out(
    const __grid_constant__ CUtensorMap mAh, const __grid_constant__ CUtensorMap mAl,
    const __grid_constant__ CUtensorMap mBh, const __grid_constant__ CUtensorMap mBl,
    const float* __restrict__ bias, float* __restrict__ C)
{
    constexpr int NS = 3;
    constexpr uint32_t STAGE = 4 * TILE_B;
    constexpr uint32_t ALOFF = 1 * TILE_B;
    constexpr uint32_t BHOFF = 2 * TILE_B;
    constexpr uint32_t BLOFF = 3 * TILE_B;
    const int N = D_MODEL, K = HIDDEN;

    extern __shared__ char smraw[];
    uint32_t sb = (smem_u32(smraw) + 1023u) & ~1023u;
    __shared__ uint64_t mbarS[NS];
    uint32_t mb = smem_u32(mbarS);

    const int tid = threadIdx.x;
    const int wid = tid >> 5, lane = tid & 31;
    const int wm = wid & 1, wn = wid >> 1;
    const int am0 = blockIdx.y * BM;
    const int bn0 = blockIdx.x * BN;

    if (tid == 0) {
#pragma unroll
        for (int s = 0; s < NS; s++) mbar_init(mb + s * 8);
    }
    __syncthreads();

    auto issue = [&](int s) {
        if (tid != 0) return;
        int slot = s % NS;
        uint32_t bar = mb + (uint32_t)slot * 8;
        mbar_expect(bar, STAGE);
        uint32_t st = sb + (uint32_t)slot * STAGE;
        int kc = s * BKE;
        tma2d(st, &mAh, kc, am0, bar);
        tma2d(st + ALOFF, &mAl, kc, am0, bar);
        tma2d(st + BHOFF, &mBh, kc, bn0, bar);
        tma2d(st + BLOFF, &mBl, kc, bn0, bar);
    };
    const int NCH = K / BKE;   // 32
#pragma unroll
    for (int s = 0; s < NS; s++) issue(s);

    float acc[4][4][4];
#pragma unroll
    for (int i = 0; i < 4; i++)
#pragma unroll
        for (int j = 0; j < 4; j++)
#pragma unroll
            for (int v = 0; v < 4; v++) acc[i][j][v] = 0.f;

    const int arA = wm * 64 + (lane & 15);
    const int ahalf = lane >> 4;
    const uint32_t axor = (uint32_t)(arA & 7);
    uint32_t aoff[4];
#pragma unroll
    for (int mf = 0; mf < 4; mf++) aoff[mf] = (uint32_t)(arA + mf * 16) * RB;

    const int nrB = wn * 32 + (lane & 7) + ((lane >> 4) << 3);
    const int khalf = (lane >> 3) & 1;
    const uint32_t bxor = (uint32_t)(nrB & 7);
    uint32_t boff[2];
#pragma unroll
    for (int nf = 0; nf < 2; nf++) boff[nf] = (uint32_t)(nrB + nf * 16) * RB;

    uint32_t ah[2][4][4], al[2][4][4], bh[2][4][2], bl[2][4][2];

    auto load_frags = [&](int buf, uint32_t st, int ks) {
        const uint32_t asg = (((uint32_t)(ks * 2 + ahalf)) ^ axor) << 4;
        const uint32_t bsg = (((uint32_t)(ks * 2 + khalf)) ^ bxor) << 4;
#pragma unroll
        for (int nf = 0; nf < 2; nf++) {
            uint32_t rr[4];
            ldm_x4(rr, st + BHOFF + boff[nf] + bsg);
            bh[buf][nf * 2 + 0][0] = rr[0]; bh[buf][nf * 2 + 0][1] = rr[1];
            bh[buf][nf * 2 + 1][0] = rr[2]; bh[buf][nf * 2 + 1][1] = rr[3];
            ldm_x4(rr, st + BLOFF + boff[nf] + bsg);
            bl[buf][nf * 2 + 0][0] = rr[0]; bl[buf][nf * 2 + 0][1] = rr[1];
            bl[buf][nf * 2 + 1][0] = rr[2]; bl[buf][nf * 2 + 1][1] = rr[3];
        }
#pragma unroll
        for (int mf = 0; mf < 4; mf++) {
            ldm_x4(ah[buf][mf], st + aoff[mf] + asg);
            ldm_x4(al[buf][mf], st + ALOFF + aoff[mf] + asg);
        }
    };

    for (int ch = 0; ch < NCH; ch++) {
        int slot = ch % NS;
        mbar_wait(mb + (uint32_t)slot * 8, (uint32_t)((ch / NS) & 1));
        const uint32_t st = sb + (uint32_t)slot * STAGE;

        load_frags(0, st, 0);
#pragma unroll
        for (int ks = 0; ks < 4; ks++) {
            const int cur = ks & 1;
            if (ks < 3) load_frags(cur ^ 1, st, ks + 1);
#pragma unroll
            for (int mf = 0; mf < 4; mf++)
#pragma unroll
                for (int nfi = 0; nfi < 4; nfi++) {
                    mma_bf16(acc[mf][nfi], ah[cur][mf], bh[cur][nfi]);
                    mma_bf16(acc[mf][nfi], ah[cur][mf], bl[cur][nfi]);
                    mma_bf16(acc[mf][nfi], al[cur][mf], bh[cur][nfi]);
                }
        }
        __syncthreads();
        if (ch + NS < NCH) issue(ch + NS);
    }

#pragma unroll
    for (int mf = 0; mf < 4; mf++) {
        const int r0 = am0 + wm * 64 + mf * 16 + (lane >> 2);
#pragma unroll
        for (int h = 0; h < 2; h++) {
            const int row = r0 + h * 8;
#pragma unroll
            for (int nfi = 0; nfi < 4; nfi++) {
                const int col = bn0 + wn * 32 + nfi * 8 + (lane & 3) * 2;
                float v0 = acc[mf][nfi][h * 2 + 0] + bias[col];
                float v1 = acc[mf][nfi][h * 2 + 1] + bias[col + 1];
                *(float2*)&C[(size_t)row * N + col] = make_float2(v0, v1);
            }
        }
    }
}

// ---------------- dt finalize + discretization --------------------------------
__global__ void disc_kernel(const float* __restrict__ A_raw,
                            const float* __restrict__ B_ssm)
{
    int idx = blockIdx.x * blockDim.x + threadIdx.x;
    if (idx >= HIDDEN * D_STATE) return;
    int h = idx / D_STATE;
    float sum = 0.f;
#pragma unroll
    for (int p = 0; p < MTOK / BM; p++) sum += g_dtpart[p * HIDDEN + h];
    float dt = sum * (1.f / (float)MTOK);
    dt = fminf(fmaxf(dt, 1e-3f), 2.0f);
    float a = -softplusf(A_raw[idx]);
    float ad = expf(a * dt);
    float bd = (ad - 1.0f) / (a + 1e-6f) * B_ssm[idx];
    g_Ad[idx] = ad;
    g_Bd[idx] = bd;
}

// ---------------- scan pass 1: fused conv+gate + chunk-local scan (CHK=64) ----
__global__ __launch_bounds__(128) void scan1_kernel(
    const float* __restrict__ C_ssm, const float* __restrict__ conv_w,
    const float* __restrict__ conv_b)
{
    int idx = blockIdx.x * blockDim.x + threadIdx.x;  // < BATCH*NCHK*HIDDEN
    int h = idx & (HIDDEN - 1);
    int bc = idx >> 11;
    int c = bc & (NCHK - 1);

    float ad[D_STATE], bd[D_STATE], cc[D_STATE], st[D_STATE];
#pragma unroll
    for (int j = 0; j < D_STATE; j++) {
        ad[j] = g_Ad[h * D_STATE + j];
        bd[j] = g_Bd[h * D_STATE + j];
        cc[j] = C_ssm[h * D_STATE + j];
        st[j] = 0.f;
    }
    const float w0 = conv_w[h * 3 + 0], w1 = conv_w[h * 3 + 1],
                w2 = conv_w[h * 3 + 2], cb = conv_b[h];

    const int b = bc >> 5;
    const int l0 = c * CHK;
    const size_t base = ((size_t)b * SEQ + l0) * HIDDEN + h;
    const float* up = g_u + base;
    float* gp = g_g + base;

    float um = (l0 > 0) ? up[-(ptrdiff_t)HIDDEN] : 0.f;
    float cu[4], cg[4];
#pragma unroll
    for (int q = 0; q < 4; q++) {
        cu[q] = up[(size_t)q * HIDDEN];
        cg[q] = gp[(size_t)q * HIDDEN];
    }

    for (int t = 0; t < CHK; t += 4) {
        float nu[4], ng[4];
#pragma unroll
        for (int q = 0; q < 4; q++) {
            int l = l0 + t + 4 + q;
            nu[q] = (l < SEQ) ? up[(size_t)(t + 4 + q) * HIDDEN] : 0.f;
            int tt = t + 4 + q;
            ng[q] = (tt < CHK) ? gp[(size_t)tt * HIDDEN] : 0.f;
        }
#pragma unroll
        for (int q = 0; q < 4; q++) {
            float u0 = cu[q];
            float upn = (q < 3) ? cu[q + 1] : nu[0];
            float hc = cb + w0 * um + w1 * u0 + w2 * upn;
            float g = cg[q];
            float uc = u0 * g + hc * (1.f - g);
            float y0 = 0.f, y1 = 0.f, y2 = 0.f, y3 = 0.f;
#pragma unroll
            for (int j = 0; j < D_STATE; j++)
                st[j] = fmaf(ad[j], st[j], bd[j] * uc);
#pragma unroll
            for (int j = 0; j < D_STATE; j += 4) {
                y0 = fmaf(st[j + 0], cc[j + 0], y0);
                y1 = fmaf(st[j + 1], cc[j + 1], y1);
                y2 = fmaf(st[j + 2], cc[j + 2], y2);
                y3 = fmaf(st[j + 3], cc[j + 3], y3);
            }
            gp[(size_t)(t + q) * HIDDEN] = (y0 + y1) + (y2 + y3);
            um = u0;
        }
#pragma unroll
        for (int q = 0; q < 4; q++) { cu[q] = nu[q]; cg[q] = ng[q]; }
    }
    float* sp = g_state + (size_t)idx * D_STATE;
#pragma unroll
    for (int j = 0; j < D_STATE; j += 4)
        *(float4*)&sp[j] = make_float4(st[j], st[j + 1], st[j + 2], st[j + 3]);
}

// ---------------- scan pass 2: chunk-state prefix (NCHK=32) -------------------
__global__ __launch_bounds__(256) void scan2_kernel()
{
    int idx = blockIdx.x * blockDim.x + threadIdx.x;  // < BATCH*HIDDEN*16
    int j = idx & (D_STATE - 1);
    int h = (idx >> 4) & (HIDDEN - 1);
    int b = idx >> 15;

    float ad = g_Ad[h * D_STATE + j];
    float af = ad;
#pragma unroll
    for (int i = 0; i < 6; i++) af = af * af;     // ad^64

    float carry = 0.f;
#pragma unroll
    for (int c = 0; c < NCHK; c++) {
        size_t off = (((size_t)b * NCHK + c) * HIDDEN + h) * D_STATE + j;
        g_init[off] = carry;
        carry = fmaf(af, carry, g_state[off]);
    }
}

// ---------------- scan pass 3: fixup + bf16 split (CHK=64) --------------------
__global__ __launch_bounds__(128) void scan3_kernel(const float* __restrict__ C_ssm)
{
    int idx = blockIdx.x * blockDim.x + threadIdx.x;
    int h = idx & (HIDDEN - 1);
    int bc = idx >> 11;
    int c = bc & (NCHK - 1);
    int b = bc >> 5;

    const size_t base = ((size_t)b * SEQ + (size_t)c * CHK) * HIDDEN + h;
    const float* yp = g_g + base;
    __nv_bfloat16* yh = g_yhi + base;
    __nv_bfloat16* yl = g_ylo + base;

    if (c == 0) {
        for (int t = 0; t < CHK; t++) {
            float yv = yp[(size_t)t * HIDDEN];
            __nv_bfloat16 hi = __float2bfloat16(yv);
            __nv_bfloat16 lo = __float2bfloat16(yv - __bfloat162float(hi));
            yh[(size_t)t * HIDDEN] = hi;
            yl[(size_t)t * HIDDEN] = lo;
        }
        return;
    }

    float ad[D_STATE], cc[D_STATE], p[D_STATE];
    const float* ip = g_init + (size_t)idx * D_STATE;
#pragma unroll
    for (int j = 0; j < D_STATE; j++) {
        ad[j] = g_Ad[h * D_STATE + j];
        cc[j] = C_ssm[h * D_STATE + j];
        p[j] = ip[j];
    }
    for (int t = 0; t < CHK; t++) {
        float y0 = 0.f, y1 = 0.f, y2 = 0.f, y3 = 0.f;
#pragma unroll
        for (int j = 0; j < D_STATE; j++) p[j] *= ad[j];
#pragma unroll
        for (int j = 0; j < D_STATE; j += 4) {
            y0 = fmaf(p[j + 0], cc[j + 0], y0);
            y1 = fmaf(p[j + 1], cc[j + 1], y1);
            y2 = fmaf(p[j + 2], cc[j + 2], y2);
            y3 = fmaf(p[j + 3], cc[j + 3], y3);
        }
        float yv = yp[(size_t)t * HIDDEN] + ((y0 + y1) + (y2 + y3));
        __nv_bfloat16 hi = __float2bfloat16(yv);
        __nv_bfloat16 lo = __float2bfloat16(yv - __bfloat162float(hi));
        yh[(size_t)t * HIDDEN] = hi;
        yl[(size_t)t * HIDDEN] = lo;
    }
}

// ---------------- residual + layernorm ---------------------------------------
__global__ __launch_bounds__(256) void ln_kernel(
    const float* __restrict__ x, const float* __restrict__ lng,
    const float* __restrict__ lnb, float* __restrict__ out)
{
    int row = blockIdx.x;
    __shared__ float sh[D_MODEL];
    __shared__ float rs[20];
    const float* xr = x + (size_t)row * D_MODEL;
    const float* orow = g_outp + (size_t)row * D_MODEL;
    int tid = threadIdx.x;

    float s = 0.f, sq = 0.f;
    for (int i = tid; i < D_MODEL; i += 256) {
        float r = xr[i] + orow[i];
        sh[i] = r;
        s += r;
        sq += r * r;
    }
#pragma unroll
    for (int o = 16; o > 0; o >>= 1) {
        s += __shfl_xor_sync(0xffffffffu, s, o);
        sq += __shfl_xor_sync(0xffffffffu, sq, o);
    }
    int w = tid >> 5, ln = tid & 31;
    if (ln == 0) { rs[w] = s; rs[8 + w] = sq; }
    __syncthreads();
    if (tid == 0) {
        float ts = 0.f, tq = 0.f;
#pragma unroll
        for (int i = 0; i < 8; i++) { ts += rs[i]; tq += rs[8 + i]; }
        float mean = ts * (1.f / (float)D_MODEL);
        float var = tq * (1.f / (float)D_MODEL) - mean * mean;
        rs[16] = mean;
        rs[17] = rsqrtf(var + 1e-5f);
    }
    __syncthreads();
    float mean = rs[16], inv = rs[17];
    for (int i = tid; i < D_MODEL; i += 256)
        out[(size_t)row * D_MODEL + i] = (sh[i] - mean) * inv * lng[i] + lnb[i];
}

// ---------------- host: tensormap encode via dlopen ---------------------------
typedef CUresult (*PFN_encode)(CUtensorMap*, CUtensorMapDataType, cuuint32_t, void*,
    const cuuint64_t*, const cuuint64_t*, const cuuint32_t*, const cuuint32_t*,
    CUtensorMapInterleave, CUtensorMapSwizzle, CUtensorMapL2promotion,
    CUtensorMapFloatOOBfill);

static void make_map(PFN_encode enc, CUtensorMap* m, void* ptr, int rows, int K)
{
    cuuint64_t dims[2] = {(cuuint64_t)K, (cuuint64_t)rows};
    cuuint64_t strides[1] = {(cuuint64_t)K * 2};
    cuuint32_t box[2] = {64u, 128u};
    cuuint32_t es[2] = {1u, 1u};
    enc(m, CU_TENSOR_MAP_DATA_TYPE_BFLOAT16, 2, ptr, dims, strides, box, es,
        CU_TENSOR_MAP_INTERLEAVE_NONE, CU_TENSOR_MAP_SWIZZLE_128B,
        CU_TENSOR_MAP_L2_PROMOTION_L2_128B, CU_TENSOR_MAP_FLOAT_OOB_FILL_NONE);
}

// ---------------- launch -----------------------------------------------------
extern "C" void kernel_launch(void* const* d_in, const int* in_sizes, int n_in,
                              void* d_out, int out_size)
{
    const float* x      = (const float*)d_in[0];
    const float* W_x    = (const float*)d_in[1];
    const float* b_x    = (const float*)d_in[2];
    const float* W_g    = (const float*)d_in[3];
    const float* b_g    = (const float*)d_in[4];
    const float* conv_w = (const float*)d_in[5];
    const float* conv_b = (const float*)d_in[6];
    const float* A_raw  = (const float*)d_in[7];
    const float* B_ssm  = (const float*)d_in[8];
    const float* C_ssm  = (const float*)d_in[9];
    const float* W_dt   = (const float*)d_in[10];
    const float* b_dt   = (const float*)d_in[11];
    const float* W_out  = (const float*)d_in[12];
    const float* b_out  = (const float*)d_in[13];
    const float* ln_g   = (const float*)d_in[14];
    const float* ln_b   = (const float*)d_in[15];
    float* out = (float*)d_out;

    float *pu, *pg, *pdt, *pout;
    __nv_bfloat16 *pxh, *pxl, *pwxh, *pwxl, *pwgh, *pwdh, *pwoh, *pwol, *pyh, *pyl;
    cudaGetSymbolAddress((void**)&pu, g_u);
    cudaGetSymbolAddress((void**)&pg, g_g);
    cudaGetSymbolAddress((void**)&pdt, g_dtpart);
    cudaGetSymbolAddress((void**)&pout, g_outp);
    cudaGetSymbolAddress((void**)&pxh, g_xhi);
    cudaGetSymbolAddress((void**)&pxl, g_xlo);
    cudaGetSymbolAddress((void**)&pwxh, g_wxhi);
    cudaGetSymbolAddress((void**)&pwxl, g_wxlo);
    cudaGetSymbolAddress((void**)&pwgh, g_wghi);
    cudaGetSymbolAddress((void**)&pwdh, g_wdthi);
    cudaGetSymbolAddress((void**)&pwoh, g_wohi);
    cudaGetSymbolAddress((void**)&pwol, g_wolo);
    cudaGetSymbolAddress((void**)&pyh, g_yhi);
    cudaGetSymbolAddress((void**)&pyl, g_ylo);

    void* dl = dlopen("libcuda.so.1", RTLD_NOW);
    if (!dl) dl = dlopen("libcuda.so", RTLD_NOW);
    PFN_encode enc = dl ? (PFN_encode)dlsym(dl, "cuTensorMapEncodeTiled") : nullptr;

    CUtensorMap Mxh, Mxl, Mwxh, Mwxl, Mwgh, Mwdh, Mwoh, Mwol, Myh, Myl;
    make_map(enc, &Mxh, pxh, MTOK, D_MODEL);
    make_map(enc, &Mxl, pxl, MTOK, D_MODEL);
    make_map(enc, &Mwxh, pwxh, HIDDEN, D_MODEL);
    make_map(enc, &Mwxl, pwxl, HIDDEN, D_MODEL);
    make_map(enc, &Mwgh, pwgh, HIDDEN, D_MODEL);
    make_map(enc, &Mwdh, pwdh, HIDDEN, D_MODEL);
    make_map(enc, &Mwoh, pwoh, D_MODEL, HIDDEN);
    make_map(enc, &Mwol, pwol, D_MODEL, HIDDEN);
    make_map(enc, &Myh, pyh, MTOK, HIDDEN);
    make_map(enc, &Myl, pyl, MTOK, HIDDEN);

    cudaFuncSetAttribute(gemm_ug_tma, cudaFuncAttributeMaxDynamicSharedMemorySize, SMEM_UG);
    cudaFuncSetAttribute(gemm_out, cudaFuncAttributeMaxDynamicSharedMemorySize, SMEM_OUT);
    cudaFuncSetAttribute(gemm_dt, cudaFuncAttributeMaxDynamicSharedMemorySize, SMEM_DT);

    cudaStream_t s1;
    cudaStreamCreateWithFlags(&s1, cudaStreamNonBlocking);
    cudaEvent_t eX, eW, eJoin;
    cudaEventCreateWithFlags(&eX, cudaEventDisableTiming);
    cudaEventCreateWithFlags(&eW, cudaEventDisableTiming);
    cudaEventCreateWithFlags(&eJoin, cudaEventDisableTiming);

    // fork immediately: s1 runs split_w concurrently with split_x on main
    cudaEventRecord(eX, 0);            // marks stream-0 "start" for s1 ordering
    cudaStreamWaitEvent(s1, eX, 0);
    split_w_kernel<<<(4 * WN4) / 256, 256, 0, s1>>>((const float4*)W_x,
                                                    (const float4*)W_g,
                                                    (const float4*)W_dt,
                                                    (const float4*)W_out);
    cudaEventRecord(eW, s1);

    {
        int n4 = MTOK * D_MODEL / 4;
        split_kernel<<<(n4 + 255) / 256, 256>>>((const float4*)x,
                                                (__nv_bfloat162*)pxh,
                                                (__nv_bfloat162*)pxl, n4);
    }
    cudaEventRecord(eX, 0);            // re-record: now marks split_x done

    dim3 gridH(HIDDEN / BN, MTOK / BM);    // (16, 32)
    dim3 gridD(D_MODEL / BN, MTOK / BM);   // (8, 32)

    // main: ug GEMM needs split_x (in-stream) + split_w (eW)
    cudaStreamWaitEvent(0, eW, 0);
    gemm_ug_tma<<<gridH, 256, SMEM_UG>>>(Mxh, Mxl, Mwxh, Mwxl, Mwgh,
                                         b_x, b_g, pu, pg);

    // s1: dt GEMM needs split_w (in-stream) + split_x (eX)
    cudaStreamWaitEvent(s1, eX, 0);
    gemm_dt<<<gridH, 256, SMEM_DT, s1>>>(Mxh, Mwdh, b_dt, pdt);
    disc_kernel<<<(HIDDEN * D_STATE + 255) / 256, 256, 0, s1>>>(A_raw, B_ssm);
    cudaEventRecord(eJoin, s1);

    cudaStreamWaitEvent(0, eJoin, 0);

    scan1_kernel<<<(BATCH * NCHK * HIDDEN) / 128, 128>>>(C_ssm, conv_w, conv_b);
    scan2_kernel<<<(BATCH * HIDDEN * D_STATE) / 256, 256>>>();
    scan3_kernel<<<(BATCH * NCHK * HIDDEN) / 128, 128>>>(C_ssm);

    gemm_out<<<gridD, 256, SMEM_OUT>>>(Myh, Myl, Mwoh, Mwol, b_out, pout);

    ln_kernel<<<MTOK, 256>>>(x, ln_g, ln_b, out);

    cudaEventDestroy(eX);
    cudaEventDestroy(eW);
    cudaEventDestroy(eJoin);
    cudaStreamDestroy(s1);
}

// round 14
// speedup vs baseline: 1.0436x; 1.0436x over previous
#include <cuda_runtime.h>
#include <cuda_bf16.h>
#include <cuda.h>
#include <dlfcn.h>
#include <cstdint>

#define D_MODEL 1024
#define HIDDEN  2048
#define D_STATE 16
#define BATCH   2
#define SEQ     2048
#define MTOK    4096
#define NCHK    16
#define CHK     128

// ---------------- GEMM tiling -------------------------------------------------
#define BM 128
#define BN 128
#define BKE 64
#define RB 128
#define TILE_B (128 * 128)
#define SMEM_U    (2 * 4 * TILE_B + 1024)   // 132096: u GEMM, NS=2, 4 tiles
#define SMEM_GATE (2 * 3 * TILE_B + 1024)   // 99328 : gate GEMM, NS=2, 3 tiles
#define SMEM_OUT  (3 * 4 * TILE_B + 1024)   // 197632: out GEMM, NS=3, 4 tiles
#define SMEM_DT   (3 * 2 * TILE_B + 1024)   // 99328 : dt GEMM, NS=3, 2 tiles

// ---------------- scratch ----------------------------------------------------
__device__ float g_u[(size_t)MTOK * HIDDEN];
__device__ float g_g[(size_t)MTOK * HIDDEN];
__device__ float g_outp[(size_t)MTOK * D_MODEL];
__device__ float g_dtpart[(MTOK / BM) * HIDDEN];
__device__ float g_Ad[HIDDEN * D_STATE];
__device__ float g_Bd[HIDDEN * D_STATE];
__device__ float g_state[(size_t)BATCH * NCHK * HIDDEN * D_STATE];
__device__ float g_init[(size_t)BATCH * NCHK * HIDDEN * D_STATE];

__device__ __nv_bfloat16 g_xhi[(size_t)MTOK * D_MODEL];
__device__ __nv_bfloat16 g_xlo[(size_t)MTOK * D_MODEL];
__device__ __nv_bfloat16 g_wxhi[HIDDEN * D_MODEL];
__device__ __nv_bfloat16 g_wxlo[HIDDEN * D_MODEL];
__device__ __nv_bfloat16 g_wghi[HIDDEN * D_MODEL];
__device__ __nv_bfloat16 g_wdthi[HIDDEN * D_MODEL];
__device__ __nv_bfloat16 g_wohi[D_MODEL * HIDDEN];
__device__ __nv_bfloat16 g_wolo[D_MODEL * HIDDEN];
__device__ __nv_bfloat16 g_yhi[(size_t)MTOK * HIDDEN];
__device__ __nv_bfloat16 g_ylo[(size_t)MTOK * HIDDEN];

// ---------------- helpers ----------------------------------------------------
__device__ __forceinline__ float softplusf(float x) {
    return fmaxf(x, 0.f) + log1pf(expf(-fabsf(x)));
}
__device__ __forceinline__ float sigmoidf_(float x) {
    return 1.f / (1.f + expf(-x));
}
__device__ __forceinline__ uint32_t smem_u32(const void* p) {
    uint32_t a;
    asm("{ .reg .u64 t; cvta.to.shared.u64 t, %1; cvt.u32.u64 %0, t; }"
        : "=r"(a) : "l"(p));
    return a;
}
__device__ __forceinline__ void ldm_x4(uint32_t* r, uint32_t addr) {
    asm volatile("ldmatrix.sync.aligned.m8n8.x4.shared.b16 {%0,%1,%2,%3}, [%4];"
                 : "=r"(r[0]), "=r"(r[1]), "=r"(r[2]), "=r"(r[3]) : "r"(addr));
}
__device__ __forceinline__ void mma_bf16(float* d, const uint32_t* a,
                                         const uint32_t* b) {
    asm volatile(
        "mma.sync.aligned.m16n8k16.row.col.f32.bf16.bf16.f32 "
        "{%0,%1,%2,%3}, {%4,%5,%6,%7}, {%8,%9}, {%0,%1,%2,%3};"
        : "+f"(d[0]), "+f"(d[1]), "+f"(d[2]), "+f"(d[3])
        : "r"(a[0]), "r"(a[1]), "r"(a[2]), "r"(a[3]), "r"(b[0]), "r"(b[1]));
}
__device__ __forceinline__ void mbar_init(uint32_t addr) {
    asm volatile("mbarrier.init.shared.b64 [%0], 1;" :: "r"(addr) : "memory");
}
__device__ __forceinline__ void mbar_expect(uint32_t addr, uint32_t bytes) {
    asm volatile("mbarrier.arrive.expect_tx.shared.b64 _, [%0], %1;"
                 :: "r"(addr), "r"(bytes) : "memory");
}
__device__ __forceinline__ void mbar_wait(uint32_t addr, uint32_t parity) {
    asm volatile(
        "{\n\t.reg .pred P;\n\t"
        "W_%=:\n\t"
        "mbarrier.try_wait.parity.acquire.cta.shared::cta.b64 P, [%0], %1, 0x989680;\n\t"
        "@P bra D_%=;\n\t"
        "bra W_%=;\n\t"
        "D_%=:\n\t}"
        :: "r"(addr), "r"(parity) : "memory");
}
__device__ __forceinline__ void tma2d(uint32_t smaddr, const CUtensorMap* m,
                                      int cx, int cy, uint32_t mbar) {
    asm volatile(
        "cp.async.bulk.tensor.2d.shared::cta.global.tile.mbarrier::complete_tx::bytes "
        "[%0], [%1, {%2, %3}], [%4];"
        :: "r"(smaddr), "l"(m), "r"(cx), "r"(cy), "r"(mbar) : "memory");
}

// ---------------- fp32 -> bf16 hi/lo split (x) --------------------------------
__global__ __launch_bounds__(256) void split_kernel(
    const float4* __restrict__ src, __nv_bfloat162* __restrict__ hi,
    __nv_bfloat162* __restrict__ lo, int n4)
{
    int i = blockIdx.x * blockDim.x + threadIdx.x;
    if (i >= n4) return;
    float4 v = src[i];
    __nv_bfloat16 h0 = __float2bfloat16(v.x);
    __nv_bfloat16 h1 = __float2bfloat16(v.y);
    __nv_bfloat16 h2 = __float2bfloat16(v.z);
    __nv_bfloat16 h3 = __float2bfloat16(v.w);
    hi[i * 2 + 0] = __nv_bfloat162(h0, h1);
    hi[i * 2 + 1] = __nv_bfloat162(h2, h3);
    if (lo) {
        __nv_bfloat16 l0 = __float2bfloat16(v.x - __bfloat162float(h0));
        __nv_bfloat16 l1 = __float2bfloat16(v.y - __bfloat162float(h1));
        __nv_bfloat16 l2 = __float2bfloat16(v.z - __bfloat162float(h2));
        __nv_bfloat16 l3 = __float2bfloat16(v.w - __bfloat162float(h3));
        lo[i * 2 + 0] = __nv_bfloat162(l0, l1);
        lo[i * 2 + 1] = __nv_bfloat162(l2, l3);
    }
}

// ---------------- fused weight split ------------------------------------------
#define WN4 (HIDDEN * D_MODEL / 4)   // 524288 = 2^19
__global__ __launch_bounds__(256) void split_w_kernel(
    const float4* __restrict__ wx, const float4* __restrict__ wg,
    const float4* __restrict__ wdt, const float4* __restrict__ wo)
{
    int gi = blockIdx.x * blockDim.x + threadIdx.x;
    int arr = gi >> 19;
    int i = gi & (WN4 - 1);
    const float4* src = (arr == 0) ? wx : (arr == 1) ? wg : (arr == 2) ? wdt : wo;
    __nv_bfloat162* hi = (arr == 0) ? (__nv_bfloat162*)g_wxhi
                       : (arr == 1) ? (__nv_bfloat162*)g_wghi
                       : (arr == 2) ? (__nv_bfloat162*)g_wdthi
                                    : (__nv_bfloat162*)g_wohi;
    __nv_bfloat162* lo = (arr == 0) ? (__nv_bfloat162*)g_wxlo
                       : (arr == 3) ? (__nv_bfloat162*)g_wolo : nullptr;
    float4 v = src[i];
    __nv_bfloat16 h0 = __float2bfloat16(v.x);
    __nv_bfloat16 h1 = __float2bfloat16(v.y);
    __nv_bfloat16 h2 = __float2bfloat16(v.z);
    __nv_bfloat16 h3 = __float2bfloat16(v.w);
    hi[i * 2 + 0] = __nv_bfloat162(h0, h1);
    hi[i * 2 + 1] = __nv_bfloat162(h2, h3);
    if (lo) {
        __nv_bfloat16 l0 = __float2bfloat16(v.x - __bfloat162float(h0));
        __nv_bfloat16 l1 = __float2bfloat16(v.y - __bfloat162float(h1));
        __nv_bfloat16 l2 = __float2bfloat16(v.z - __bfloat162float(h2));
        __nv_bfloat16 l3 = __float2bfloat16(v.w - __bfloat162float(h3));
        lo[i * 2 + 0] = __nv_bfloat162(l0, l1);
        lo[i * 2 + 1] = __nv_bfloat162(l2, l3);
    }
}

// ---------------- u GEMM: 3-term, NS=2, 4 tiles (128x128) ---------------------
__global__ __launch_bounds__(256, 1) void gemm_u(
    const __grid_constant__ CUtensorMap mAh, const __grid_constant__ CUtensorMap mAl,
    const __grid_constant__ CUtensorMap mBh, const __grid_constant__ CUtensorMap mBl,
    const float* __restrict__ bias, float* __restrict__ C)
{
    constexpr uint32_t STAGE = 4 * TILE_B;
    constexpr uint32_t ALOFF = 1 * TILE_B;
    constexpr uint32_t BHOFF = 2 * TILE_B;
    constexpr uint32_t BLOFF = 3 * TILE_B;
    const int N = HIDDEN, K = D_MODEL;

    extern __shared__ char smraw[];
    uint32_t sb = (smem_u32(smraw) + 1023u) & ~1023u;
    __shared__ uint64_t mbarS[2];
    uint32_t mb = smem_u32(mbarS);

    const int tid = threadIdx.x;
    const int wid = tid >> 5, lane = tid & 31;
    const int wm = wid & 1, wn = wid >> 1;
    const int am0 = blockIdx.y * BM;
    const int bn0 = blockIdx.x * BN;

    if (tid == 0) { mbar_init(mb); mbar_init(mb + 8); }
    __syncthreads();

    auto issue = [&](int s) {
        if (tid != 0) return;
        uint32_t bar = mb + (uint32_t)(s & 1) * 8;
        mbar_expect(bar, STAGE);
        uint32_t st = sb + (uint32_t)(s & 1) * STAGE;
        int kc = s * BKE;
        tma2d(st, &mAh, kc, am0, bar);
        tma2d(st + ALOFF, &mAl, kc, am0, bar);
        tma2d(st + BHOFF, &mBh, kc, bn0, bar);
        tma2d(st + BLOFF, &mBl, kc, bn0, bar);
    };
    issue(0); issue(1);

    float acc[4][4][4];
#pragma unroll
    for (int i = 0; i < 4; i++)
#pragma unroll
        for (int j = 0; j < 4; j++)
#pragma unroll
            for (int v = 0; v < 4; v++) acc[i][j][v] = 0.f;

    const int arA = wm * 64 + (lane & 15);
    const int ahalf = lane >> 4;
    const uint32_t axor = (uint32_t)(arA & 7);
    uint32_t aoff[4];
#pragma unroll
    for (int mf = 0; mf < 4; mf++) aoff[mf] = (uint32_t)(arA + mf * 16) * RB;

    const int nrB = wn * 32 + (lane & 7) + ((lane >> 4) << 3);
    const int khalf = (lane >> 3) & 1;
    const uint32_t bxor = (uint32_t)(nrB & 7);
    uint32_t boff[2];
#pragma unroll
    for (int nf = 0; nf < 2; nf++) boff[nf] = (uint32_t)(nrB + nf * 16) * RB;

    const int NCH = K / BKE;   // 16
    for (int ch = 0; ch < NCH; ch++) {
        mbar_wait(mb + (uint32_t)(ch & 1) * 8, (uint32_t)((ch >> 1) & 1));
        const uint32_t st = sb + (uint32_t)(ch & 1) * STAGE;

#pragma unroll
        for (int ks = 0; ks < 4; ks++) {
            const uint32_t asg = (((uint32_t)(ks * 2 + ahalf)) ^ axor) << 4;
            const uint32_t bsg = (((uint32_t)(ks * 2 + khalf)) ^ bxor) << 4;
            uint32_t ah[4][4], al[4][4], bh[4][2], bl[4][2];
#pragma unroll
            for (int nf = 0; nf < 2; nf++) {
                uint32_t rr[4];
                ldm_x4(rr, st + BHOFF + boff[nf] + bsg);
                bh[nf * 2 + 0][0] = rr[0]; bh[nf * 2 + 0][1] = rr[1];
                bh[nf * 2 + 1][0] = rr[2]; bh[nf * 2 + 1][1] = rr[3];
                ldm_x4(rr, st + BLOFF + boff[nf] + bsg);
                bl[nf * 2 + 0][0] = rr[0]; bl[nf * 2 + 0][1] = rr[1];
                bl[nf * 2 + 1][0] = rr[2]; bl[nf * 2 + 1][1] = rr[3];
            }
#pragma unroll
            for (int mf = 0; mf < 4; mf++) {
                ldm_x4(ah[mf], st + aoff[mf] + asg);
                ldm_x4(al[mf], st + ALOFF + aoff[mf] + asg);
            }
#pragma unroll
            for (int mf = 0; mf < 4; mf++)
#pragma unroll
                for (int nfi = 0; nfi < 4; nfi++) {
                    mma_bf16(acc[mf][nfi], ah[mf], bh[nfi]);
                    mma_bf16(acc[mf][nfi], ah[mf], bl[nfi]);
                    mma_bf16(acc[mf][nfi], al[mf], bh[nfi]);
                }
        }
        __syncthreads();
        if (ch + 2 < NCH) issue(ch + 2);
    }

#pragma unroll
    for (int mf = 0; mf < 4; mf++) {
        const int r0 = am0 + wm * 64 + mf * 16 + (lane >> 2);
#pragma unroll
        for (int h = 0; h < 2; h++) {
            const int row = r0 + h * 8;
#pragma unroll
            for (int nfi = 0; nfi < 4; nfi++) {
                const int col = bn0 + wn * 32 + nfi * 8 + (lane & 3) * 2;
                float v0 = acc[mf][nfi][h * 2 + 0] + bias[col];
                float v1 = acc[mf][nfi][h * 2 + 1] + bias[col + 1];
                *(float2*)&C[(size_t)row * N + col] = make_float2(v0, v1);
            }
        }
    }
}

// ---------------- gate GEMM: 2-term (Wg hi only), NS=2, 3 tiles, 2 CTA-able ---
__global__ __launch_bounds__(256, 2) void gemm_gate(
    const __grid_constant__ CUtensorMap mAh, const __grid_constant__ CUtensorMap mAl,
    const __grid_constant__ CUtensorMap mGh,
    const float* __restrict__ bias, float* __restrict__ C)
{
    constexpr uint32_t STAGE = 3 * TILE_B;
    constexpr uint32_t ALOFF = 1 * TILE_B;
    constexpr uint32_t GHOFF = 2 * TILE_B;
    const int N = HIDDEN, K = D_MODEL;

    extern __shared__ char smraw[];
    uint32_t sb = (smem_u32(smraw) + 1023u) & ~1023u;
    __shared__ uint64_t mbarS[2];
    uint32_t mb = smem_u32(mbarS);

    const int tid = threadIdx.x;
    const int wid = tid >> 5, lane = tid & 31;
    const int wm = wid & 1, wn = wid >> 1;
    const int am0 = blockIdx.y * BM;
    const int bn0 = blockIdx.x * BN;

    if (tid == 0) { mbar_init(mb); mbar_init(mb + 8); }
    __syncthreads();

    auto issue = [&](int s) {
        if (tid != 0) return;
        uint32_t bar = mb + (uint32_t)(s & 1) * 8;
        mbar_expect(bar, STAGE);
        uint32_t st = sb + (uint32_t)(s & 1) * STAGE;
        int kc = s * BKE;
        tma2d(st, &mAh, kc, am0, bar);
        tma2d(st + ALOFF, &mAl, kc, am0, bar);
        tma2d(st + GHOFF, &mGh, kc, bn0, bar);
    };
    issue(0); issue(1);

    float acc[4][4][4];
#pragma unroll
    for (int i = 0; i < 4; i++)
#pragma unroll
        for (int j = 0; j < 4; j++)
#pragma unroll
            for (int v = 0; v < 4; v++) acc[i][j][v] = 0.f;

    const int arA = wm * 64 + (lane & 15);
    const int ahalf = lane >> 4;
    const uint32_t axor = (uint32_t)(arA & 7);
    uint32_t aoff[4];
#pragma unroll
    for (int mf = 0; mf < 4; mf++) aoff[mf] = (uint32_t)(arA + mf * 16) * RB;

    const int nrB = wn * 32 + (lane & 7) + ((lane >> 4) << 3);
    const int khalf = (lane >> 3) & 1;
    const uint32_t bxor = (uint32_t)(nrB & 7);
    uint32_t boff[2];
#pragma unroll
    for (int nf = 0; nf < 2; nf++) boff[nf] = (uint32_t)(nrB + nf * 16) * RB;

    const int NCH = K / BKE;   // 16
    for (int ch = 0; ch < NCH; ch++) {
        mbar_wait(mb + (uint32_t)(ch & 1) * 8, (uint32_t)((ch >> 1) & 1));
        const uint32_t st = sb + (uint32_t)(ch & 1) * STAGE;

#pragma unroll
        for (int ks = 0; ks < 4; ks++) {
            const uint32_t asg = (((uint32_t)(ks * 2 + ahalf)) ^ axor) << 4;
            const uint32_t bsg = (((uint32_t)(ks * 2 + khalf)) ^ bxor) << 4;
            uint32_t ah[4][4], al[4][4], gh[4][2];
#pragma unroll
            for (int nf = 0; nf < 2; nf++) {
                uint32_t rr[4];
                ldm_x4(rr, st + GHOFF + boff[nf] + bsg);
                gh[nf * 2 + 0][0] = rr[0]; gh[nf * 2 + 0][1] = rr[1];
                gh[nf * 2 + 1][0] = rr[2]; gh[nf * 2 + 1][1] = rr[3];
            }
#pragma unroll
            for (int mf = 0; mf < 4; mf++) {
                ldm_x4(ah[mf], st + aoff[mf] + asg);
                ldm_x4(al[mf], st + ALOFF + aoff[mf] + asg);
            }
#pragma unroll
            for (int mf = 0; mf < 4; mf++)
#pragma unroll
                for (int nfi = 0; nfi < 4; nfi++) {
                    mma_bf16(acc[mf][nfi], ah[mf], gh[nfi]);
                    mma_bf16(acc[mf][nfi], al[mf], gh[nfi]);
                }
        }
        __syncthreads();
        if (ch + 2 < NCH) issue(ch + 2);
    }

#pragma unroll
    for (int mf = 0; mf < 4; mf++) {
        const int r0 = am0 + wm * 64 + mf * 16 + (lane >> 2);
#pragma unroll
        for (int h = 0; h < 2; h++) {
            const int row = r0 + h * 8;
#pragma unroll
            for (int nfi = 0; nfi < 4; nfi++) {
                const int col = bn0 + wn * 32 + nfi * 8 + (lane & 3) * 2;
                float g0 = sigmoidf_(acc[mf][nfi][h * 2 + 0] + bias[col]);
                float g1 = sigmoidf_(acc[mf][nfi][h * 2 + 1] + bias[col + 1]);
                *(float2*)&C[(size_t)row * N + col] = make_float2(g0, g1);
            }
        }
    }
}

// ---------------- dt GEMM: 1-term, NS=3, 2 CTAs/SM ----------------------------
__global__ __launch_bounds__(256, 2) void gemm_dt(
    const __grid_constant__ CUtensorMap mAh, const __grid_constant__ CUtensorMap mBh,
    const float* __restrict__ bias, float* __restrict__ colsum)
{
    constexpr int NS = 3;
    constexpr uint32_t STAGE = 2 * TILE_B;
    constexpr uint32_t BHOFF = TILE_B;
    const int N = HIDDEN, K = D_MODEL;

    extern __shared__ char smraw[];
    uint32_t sb = (smem_u32(smraw) + 1023u) & ~1023u;
    __shared__ uint64_t mbarS[NS];
    uint32_t mb = smem_u32(mbarS);

    const int tid = threadIdx.x;
    const int wid = tid >> 5, lane = tid & 31;
    const int wm = wid & 1, wn = wid >> 1;
    const int am0 = blockIdx.y * BM;
    const int bn0 = blockIdx.x * BN;

    if (tid == 0) {
#pragma unroll
        for (int s = 0; s < NS; s++) mbar_init(mb + s * 8);
    }
    __syncthreads();

    auto issue = [&](int s) {
        if (tid != 0) return;
        int slot = s % NS;
        uint32_t bar = mb + (uint32_t)slot * 8;
        mbar_expect(bar, STAGE);
        uint32_t st = sb + (uint32_t)slot * STAGE;
        int kc = s * BKE;
        tma2d(st, &mAh, kc, am0, bar);
        tma2d(st + BHOFF, &mBh, kc, bn0, bar);
    };
    const int NCH = K / BKE;
#pragma unroll
    for (int s = 0; s < NS; s++) if (s < NCH) issue(s);

    float acc[4][4][4];
#pragma unroll
    for (int i = 0; i < 4; i++)
#pragma unroll
        for (int j = 0; j < 4; j++)
#pragma unroll
            for (int v = 0; v < 4; v++) acc[i][j][v] = 0.f;

    const int arA = wm * 64 + (lane & 15);
    const int ahalf = lane >> 4;
    const uint32_t axor = (uint32_t)(arA & 7);
    uint32_t aoff[4];
#pragma unroll
    for (int mf = 0; mf < 4; mf++) aoff[mf] = (uint32_t)(arA + mf * 16) * RB;

    const int nrB = wn * 32 + (lane & 7) + ((lane >> 4) << 3);
    const int khalf = (lane >> 3) & 1;
    const uint32_t bxor = (uint32_t)(nrB & 7);
    uint32_t boff[2];
#pragma unroll
    for (int nf = 0; nf < 2; nf++) boff[nf] = (uint32_t)(nrB + nf * 16) * RB;

    for (int ch = 0; ch < NCH; ch++) {
        int slot = ch % NS;
        mbar_wait(mb + (uint32_t)slot * 8, (uint32_t)((ch / NS) & 1));
        const uint32_t st = sb + (uint32_t)slot * STAGE;

#pragma unroll
        for (int ks = 0; ks < 4; ks++) {
            uint32_t a[4][4], bh[4][2];
            const uint32_t asg = (((uint32_t)(ks * 2 + ahalf)) ^ axor) << 4;
            const uint32_t bsg = (((uint32_t)(ks * 2 + khalf)) ^ bxor) << 4;
#pragma unroll
            for (int nf = 0; nf < 2; nf++) {
                uint32_t rr[4];
                ldm_x4(rr, st + BHOFF + boff[nf] + bsg);
                bh[nf * 2 + 0][0] = rr[0]; bh[nf * 2 + 0][1] = rr[1];
                bh[nf * 2 + 1][0] = rr[2]; bh[nf * 2 + 1][1] = rr[3];
            }
#pragma unroll
            for (int mf = 0; mf < 4; mf++) ldm_x4(a[mf], st + aoff[mf] + asg);
#pragma unroll
            for (int mf = 0; mf < 4; mf++)
#pragma unroll
                for (int nfi = 0; nfi < 4; nfi++)
                    mma_bf16(acc[mf][nfi], a[mf], bh[nfi]);
        }
        __syncthreads();
        if (ch + NS < NCH) issue(ch + NS);
    }

    float* red = (float*)smraw;
#pragma unroll
    for (int nfi = 0; nfi < 4; nfi++) {
        const int colb = bn0 + wn * 32 + nfi * 8 + (lane & 3) * 2;
        const float b0 = bias[colb], b1 = bias[colb + 1];
        float s0 = 0.f, s1 = 0.f;
#pragma unroll
        for (int mf = 0; mf < 4; mf++) {
            s0 += softplusf(acc[mf][nfi][0] + b0);
            s1 += softplusf(acc[mf][nfi][1] + b1);
            s0 += softplusf(acc[mf][nfi][2] + b0);
            s1 += softplusf(acc[mf][nfi][3] + b1);
        }
#pragma unroll
        for (int o = 4; o <= 16; o <<= 1) {
            s0 += __shfl_xor_sync(0xffffffffu, s0, o);
            s1 += __shfl_xor_sync(0xffffffffu, s1, o);
        }
        if (lane < 4) {
            int c = wn * 32 + nfi * 8 + lane * 2;
            red[wm * 128 + c] = s0;
            red[wm * 128 + c + 1] = s1;
        }
    }
    __syncthreads();
    if (tid < 128)
        colsum[(size_t)blockIdx.y * N + bn0 + tid] = red[tid] + red[128 + tid];
}

// ---------------- out GEMM: 3-term, NS=3, ks-pipelined fragments --------------
__global__ __launch_bounds__(256, 1) void gemm_out(
    const __grid_constant__ CUtensorMap mAh, const __grid_constant__ CUtensorMap mAl,
    const __grid_constant__ CUtensorMap mBh, const __grid_constant__ CUtensorMap mBl,
    const float* __restrict__ bias, float* __restrict__ C)
{
    constexpr int NS = 3;
    constexpr uint32_t STAGE = 4 * TILE_B;
    constexpr uint32_t ALOFF = 1 * TILE_B;
    constexpr uint32_t BHOFF = 2 * TILE_B;
    constexpr uint32_t BLOFF = 3 * TILE_B;
    const int N = D_MODEL, K = HIDDEN;

    extern __shared__ char smraw[];
    uint32_t sb = (smem_u32(smraw) + 1023u) & ~1023u;
    __shared__ uint64_t mbarS[NS];
    uint32_t mb = smem_u32(mbarS);

    const int tid = threadIdx.x;
    const int wid = tid >> 5, lane = tid & 31;
    const int wm = wid & 1, wn = wid >> 1;
    const int am0 = blockIdx.y * BM;
    const int bn0 = blockIdx.x * BN;

    if (tid == 0) {
#pragma unroll
        for (int s = 0; s < NS; s++) mbar_init(mb + s * 8);
    }
    __syncthreads();

    auto issue = [&](int s) {
        if (tid != 0) return;
        int slot = s % NS;
        uint32_t bar = mb + (uint32_t)slot * 8;
        mbar_expect(bar, STAGE);
        uint32_t st = sb + (uint32_t)slot * STAGE;
        int kc = s * BKE;
        tma2d(st, &mAh, kc, am0, bar);
        tma2d(st + ALOFF, &mAl, kc, am0, bar);
        tma2d(st + BHOFF, &mBh, kc, bn0, bar);
        tma2d(st + BLOFF, &mBl, kc, bn0, bar);
    };
    const int NCH = K / BKE;   // 32
#pragma unroll
    for (int s = 0; s < NS; s++) issue(s);

    float acc[4][4][4];
#pragma unroll
    for (int i = 0; i < 4; i++)
#pragma unroll
        for (int j = 0; j < 4; j++)
#pragma unroll
            for (int v = 0; v < 4; v++) acc[i][j][v] = 0.f;

    const int arA = wm * 64 + (lane & 15);
    const int ahalf = lane >> 4;
    const uint32_t axor = (uint32_t)(arA & 7);
    uint32_t aoff[4];
#pragma unroll
    for (int mf = 0; mf < 4; mf++) aoff[mf] = (uint32_t)(arA + mf * 16) * RB;

    const int nrB = wn * 32 + (lane & 7) + ((lane >> 4) << 3);
    const int khalf = (lane >> 3) & 1;
    const uint32_t bxor = (uint32_t)(nrB & 7);
    uint32_t boff[2];
#pragma unroll
    for (int nf = 0; nf < 2; nf++) boff[nf] = (uint32_t)(nrB + nf * 16) * RB;

    uint32_t ah[2][4][4], al[2][4][4], bh[2][4][2], bl[2][4][2];

    auto load_frags = [&](int buf, uint32_t st, int ks) {
        const uint32_t asg = (((uint32_t)(ks * 2 + ahalf)) ^ axor) << 4;
        const uint32_t bsg = (((uint32_t)(ks * 2 + khalf)) ^ bxor) << 4;
#pragma unroll
        for (int nf = 0; nf < 2; nf++) {
            uint32_t rr[4];
            ldm_x4(rr, st + BHOFF + boff[nf] + bsg);
            bh[buf][nf * 2 + 0][0] = rr[0]; bh[buf][nf * 2 + 0][1] = rr[1];
            bh[buf][nf * 2 + 1][0] = rr[2]; bh[buf][nf * 2 + 1][1] = rr[3];
            ldm_x4(rr, st + BLOFF + boff[nf] + bsg);
            bl[buf][nf * 2 + 0][0] = rr[0]; bl[buf][nf * 2 + 0][1] = rr[1];
            bl[buf][nf * 2 + 1][0] = rr[2]; bl[buf][nf * 2 + 1][1] = rr[3];
        }
#pragma unroll
        for (int mf = 0; mf < 4; mf++) {
            ldm_x4(ah[buf][mf], st + aoff[mf] + asg);
            ldm_x4(al[buf][mf], st + ALOFF + aoff[mf] + asg);
        }
    };

    for (int ch = 0; ch < NCH; ch++) {
        int slot = ch % NS;
        mbar_wait(mb + (uint32_t)slot * 8, (uint32_t)((ch / NS) & 1));
        const uint32_t st = sb + (uint32_t)slot * STAGE;

        load_frags(0, st, 0);
#pragma unroll
        for (int ks = 0; ks < 4; ks++) {
            const int cur = ks & 1;
            if (ks < 3) load_frags(cur ^ 1, st, ks + 1);
#pragma unroll
            for (int mf = 0; mf < 4; mf++)
#pragma unroll
                for (int nfi = 0; nfi < 4; nfi++) {
                    mma_bf16(acc[mf][nfi], ah[cur][mf], bh[cur][nfi]);
                    mma_bf16(acc[mf][nfi], ah[cur][mf], bl[cur][nfi]);
                    mma_bf16(acc[mf][nfi], al[cur][mf], bh[cur][nfi]);
                }
        }
        __syncthreads();
        if (ch + NS < NCH) issue(ch + NS);
    }

#pragma unroll
    for (int mf = 0; mf < 4; mf++) {
        const int r0 = am0 + wm * 64 + mf * 16 + (lane >> 2);
#pragma unroll
        for (int h = 0; h < 2; h++) {
            const int row = r0 + h * 8;
#pragma unroll
            for (int nfi = 0; nfi < 4; nfi++) {
                const int col = bn0 + wn * 32 + nfi * 8 + (lane & 3) * 2;
                float v0 = acc[mf][nfi][h * 2 + 0] + bias[col];
                float v1 = acc[mf][nfi][h * 2 + 1] + bias[col + 1];
                *(float2*)&C[(size_t)row * N + col] = make_float2(v0, v1);
            }
        }
    }
}

// ---------------- dt finalize + discretization --------------------------------
__global__ void disc_kernel(const float* __restrict__ A_raw,
                            const float* __restrict__ B_ssm)
{
    int idx = blockIdx.x * blockDim.x + threadIdx.x;
    if (idx >= HIDDEN * D_STATE) return;
    int h = idx / D_STATE;
    float sum = 0.f;
#pragma unroll
    for (int p = 0; p < MTOK / BM; p++) sum += g_dtpart[p * HIDDEN + h];
    float dt = sum * (1.f / (float)MTOK);
    dt = fminf(fmaxf(dt, 1e-3f), 2.0f);
    float a = -softplusf(A_raw[idx]);
    float ad = expf(a * dt);
    float bd = (ad - 1.0f) / (a + 1e-6f) * B_ssm[idx];
    g_Ad[idx] = ad;
    g_Bd[idx] = bd;
}

// ---------------- scan pass 1: fused conv+gate + chunk-local scan -------------
__global__ __launch_bounds__(128) void scan1_kernel(
    const float* __restrict__ C_ssm, const float* __restrict__ conv_w,
    const float* __restrict__ conv_b)
{
    int idx = blockIdx.x * blockDim.x + threadIdx.x;  // < BATCH*NCHK*HIDDEN
    int h = idx & (HIDDEN - 1);
    int bc = idx >> 11;
    int c = bc & (NCHK - 1);

    float ad[D_STATE], bd[D_STATE], cc[D_STATE], st[D_STATE];
#pragma unroll
    for (int j = 0; j < D_STATE; j++) {
        ad[j] = g_Ad[h * D_STATE + j];
        bd[j] = g_Bd[h * D_STATE + j];
        cc[j] = C_ssm[h * D_STATE + j];
        st[j] = 0.f;
    }
    const float w0 = conv_w[h * 3 + 0], w1 = conv_w[h * 3 + 1],
                w2 = conv_w[h * 3 + 2], cb = conv_b[h];

    const int b = bc >> 4;
    const int l0 = c * CHK;
    const size_t base = ((size_t)b * SEQ + l0) * HIDDEN + h;
    const float* up = g_u + base;
    float* gp = g_g + base;

    float um = (l0 > 0) ? up[-(ptrdiff_t)HIDDEN] : 0.f;
    float cu[4], cg[4];
#pragma unroll
    for (int q = 0; q < 4; q++) {
        cu[q] = up[(size_t)q * HIDDEN];
        cg[q] = gp[(size_t)q * HIDDEN];
    }

    for (int t = 0; t < CHK; t += 4) {
        float nu[4], ng[4];
#pragma unroll
        for (int q = 0; q < 4; q++) {
            int l = l0 + t + 4 + q;
            nu[q] = (l < SEQ) ? up[(size_t)(t + 4 + q) * HIDDEN] : 0.f;
            int tt = t + 4 + q;
            ng[q] = (tt < CHK) ? gp[(size_t)tt * HIDDEN] : 0.f;
        }
#pragma unroll
        for (int q = 0; q < 4; q++) {
            float u0 = cu[q];
            float upn = (q < 3) ? cu[q + 1] : nu[0];
            float hc = cb + w0 * um + w1 * u0 + w2 * upn;
            float g = cg[q];
            float uc = u0 * g + hc * (1.f - g);
            float y0 = 0.f, y1 = 0.f, y2 = 0.f, y3 = 0.f;
#pragma unroll
            for (int j = 0; j < D_STATE; j++)
                st[j] = fmaf(ad[j], st[j], bd[j] * uc);
#pragma unroll
            for (int j = 0; j < D_STATE; j += 4) {
                y0 = fmaf(st[j + 0], cc[j + 0], y0);
                y1 = fmaf(st[j + 1], cc[j + 1], y1);
                y2 = fmaf(st[j + 2], cc[j + 2], y2);
                y3 = fmaf(st[j + 3], cc[j + 3], y3);
            }
            gp[(size_t)(t + q) * HIDDEN] = (y0 + y1) + (y2 + y3);
            um = u0;
        }
#pragma unroll
        for (int q = 0; q < 4; q++) { cu[q] = nu[q]; cg[q] = ng[q]; }
    }
    float* sp = g_state + (size_t)idx * D_STATE;
#pragma unroll
    for (int j = 0; j < D_STATE; j += 4)
        *(float4*)&sp[j] = make_float4(st[j], st[j + 1], st[j + 2], st[j + 3]);
}

// ---------------- scan pass 2: chunk-state prefix -----------------------------
__global__ __launch_bounds__(256) void scan2_kernel()
{
    int idx = blockIdx.x * blockDim.x + threadIdx.x;  // < BATCH*HIDDEN*16
    int j = idx & (D_STATE - 1);
    int h = (idx >> 4) & (HIDDEN - 1);
    int b = idx >> 15;

    float ad = g_Ad[h * D_STATE + j];
    float af = ad;
#pragma unroll
    for (int i = 0; i < 7; i++) af = af * af;     // ad^128

    float carry = 0.f;
#pragma unroll
    for (int c = 0; c < NCHK; c++) {
        size_t off = (((size_t)b * NCHK + c) * HIDDEN + h) * D_STATE + j;
        g_init[off] = carry;
        carry = fmaf(af, carry, g_state[off]);
    }
}

// ---------------- scan pass 3: fixup + bf16 split -----------------------------
__global__ __launch_bounds__(128) void scan3_kernel(const float* __restrict__ C_ssm)
{
    int idx = blockIdx.x * blockDim.x + threadIdx.x;
    int h = idx & (HIDDEN - 1);
    int bc = idx >> 11;
    int c = bc & (NCHK - 1);
    int b = bc >> 4;

    const size_t base = ((size_t)b * SEQ + (size_t)c * CHK) * HIDDEN + h;
    const float* yp = g_g + base;
    __nv_bfloat16* yh = g_yhi + base;
    __nv_bfloat16* yl = g_ylo + base;

    if (c == 0) {
        for (int t = 0; t < CHK; t++) {
            float yv = yp[(size_t)t * HIDDEN];
            __nv_bfloat16 hi = __float2bfloat16(yv);
            __nv_bfloat16 lo = __float2bfloat16(yv - __bfloat162float(hi));
            yh[(size_t)t * HIDDEN] = hi;
            yl[(size_t)t * HIDDEN] = lo;
        }
        return;
    }

    float ad[D_STATE], cc[D_STATE], p[D_STATE];
    const float* ip = g_init + (size_t)idx * D_STATE;
#pragma unroll
    for (int j = 0; j < D_STATE; j++) {
        ad[j] = g_Ad[h * D_STATE + j];
        cc[j] = C_ssm[h * D_STATE + j];
        p[j] = ip[j];
    }
    for (int t = 0; t < CHK; t++) {
        float y0 = 0.f, y1 = 0.f, y2 = 0.f, y3 = 0.f;
#pragma unroll
        for (int j = 0; j < D_STATE; j++) p[j] *= ad[j];
#pragma unroll
        for (int j = 0; j < D_STATE; j += 4) {
            y0 = fmaf(p[j + 0], cc[j + 0], y0);
            y1 = fmaf(p[j + 1], cc[j + 1], y1);
            y2 = fmaf(p[j + 2], cc[j + 2], y2);
            y3 = fmaf(p[j + 3], cc[j + 3], y3);
        }
        float yv = yp[(size_t)t * HIDDEN] + ((y0 + y1) + (y2 + y3));
        __nv_bfloat16 hi = __float2bfloat16(yv);
        __nv_bfloat16 lo = __float2bfloat16(yv - __bfloat162float(hi));
        yh[(size_t)t * HIDDEN] = hi;
        yl[(size_t)t * HIDDEN] = lo;
    }
}

// ---------------- residual + layernorm ---------------------------------------
__global__ __launch_bounds__(256) void ln_kernel(
    const float* __restrict__ x, const float* __restrict__ lng,
    const float* __restrict__ lnb, float* __restrict__ out)
{
    int row = blockIdx.x;
    __shared__ float sh[D_MODEL];
    __shared__ float rs[20];
    const float* xr = x + (size_t)row * D_MODEL;
    const float* orow = g_outp + (size_t)row * D_MODEL;
    int tid = threadIdx.x;

    float s = 0.f, sq = 0.f;
    for (int i = tid; i < D_MODEL; i += 256) {
        float r = xr[i] + orow[i];
        sh[i] = r;
        s += r;
        sq += r * r;
    }
#pragma unroll
    for (int o = 16; o > 0; o >>= 1) {
        s += __shfl_xor_sync(0xffffffffu, s, o);
        sq += __shfl_xor_sync(0xffffffffu, sq, o);
    }
    int w = tid >> 5, ln = tid & 31;
    if (ln == 0) { rs[w] = s; rs[8 + w] = sq; }
    __syncthreads();
    if (tid == 0) {
        float ts = 0.f, tq = 0.f;
#pragma unroll
        for (int i = 0; i < 8; i++) { ts += rs[i]; tq += rs[8 + i]; }
        float mean = ts * (1.f / (float)D_MODEL);
        float var = tq * (1.f / (float)D_MODEL) - mean * mean;
        rs[16] = mean;
        rs[17] = rsqrtf(var + 1e-5f);
    }
    __syncthreads();
    float mean = rs[16], inv = rs[17];
    for (int i = tid; i < D_MODEL; i += 256)
        out[(size_t)row * D_MODEL + i] = (sh[i] - mean) * inv * lng[i] + lnb[i];
}

// ---------------- host: tensormap encode via dlopen ---------------------------
typedef CUresult (*PFN_encode)(CUtensorMap*, CUtensorMapDataType, cuuint32_t, void*,
    const cuuint64_t*, const cuuint64_t*, const cuuint32_t*, const cuuint32_t*,
    CUtensorMapInterleave, CUtensorMapSwizzle, CUtensorMapL2promotion,
    CUtensorMapFloatOOBfill);

static void make_map(PFN_encode enc, CUtensorMap* m, void* ptr, int rows, int K)
{
    cuuint64_t dims[2] = {(cuuint64_t)K, (cuuint64_t)rows};
    cuuint64_t strides[1] = {(cuuint64_t)K * 2};
    cuuint32_t box[2] = {64u, 128u};
    cuuint32_t es[2] = {1u, 1u};
    enc(m, CU_TENSOR_MAP_DATA_TYPE_BFLOAT16, 2, ptr, dims, strides, box, es,
        CU_TENSOR_MAP_INTERLEAVE_NONE, CU_TENSOR_MAP_SWIZZLE_128B,
        CU_TENSOR_MAP_L2_PROMOTION_L2_128B, CU_TENSOR_MAP_FLOAT_OOB_FILL_NONE);
}

// ---------------- launch -----------------------------------------------------
extern "C" void kernel_launch(void* const* d_in, const int* in_sizes, int n_in,
                              void* d_out, int out_size)
{
    const float* x      = (const float*)d_in[0];
    const float* W_x    = (const float*)d_in[1];
    const float* b_x    = (const float*)d_in[2];
    const float* W_g    = (const float*)d_in[3];
    const float* b_g    = (const float*)d_in[4];
    const float* conv_w = (const float*)d_in[5];
    const float* conv_b = (const float*)d_in[6];
    const float* A_raw  = (const float*)d_in[7];
    const float* B_ssm  = (const float*)d_in[8];
    const float* C_ssm  = (const float*)d_in[9];
    const float* W_dt   = (const float*)d_in[10];
    const float* b_dt   = (const float*)d_in[11];
    const float* W_out  = (const float*)d_in[12];
    const float* b_out  = (const float*)d_in[13];
    const float* ln_g   = (const float*)d_in[14];
    const float* ln_b   = (const float*)d_in[15];
    float* out = (float*)d_out;

    float *pu, *pg, *pdt, *pout;
    __nv_bfloat16 *pxh, *pxl, *pwxh, *pwxl, *pwgh, *pwdh, *pwoh, *pwol, *pyh, *pyl;
    cudaGetSymbolAddress((void**)&pu, g_u);
    cudaGetSymbolAddress((void**)&pg, g_g);
    cudaGetSymbolAddress((void**)&pdt, g_dtpart);
    cudaGetSymbolAddress((void**)&pout, g_outp);
    cudaGetSymbolAddress((void**)&pxh, g_xhi);
    cudaGetSymbolAddress((void**)&pxl, g_xlo);
    cudaGetSymbolAddress((void**)&pwxh, g_wxhi);
    cudaGetSymbolAddress((void**)&pwxl, g_wxlo);
    cudaGetSymbolAddress((void**)&pwgh, g_wghi);
    cudaGetSymbolAddress((void**)&pwdh, g_wdthi);
    cudaGetSymbolAddress((void**)&pwoh, g_wohi);
    cudaGetSymbolAddress((void**)&pwol, g_wolo);
    cudaGetSymbolAddress((void**)&pyh, g_yhi);
    cudaGetSymbolAddress((void**)&pyl, g_ylo);

    void* dl = dlopen("libcuda.so.1", RTLD_NOW);
    if (!dl) dl = dlopen("libcuda.so", RTLD_NOW);
    PFN_encode enc = dl ? (PFN_encode)dlsym(dl, "cuTensorMapEncodeTiled") : nullptr;

    CUtensorMap Mxh, Mxl, Mwxh, Mwxl, Mwgh, Mwdh, Mwoh, Mwol, Myh, Myl;
    make_map(enc, &Mxh, pxh, MTOK, D_MODEL);
    make_map(enc, &Mxl, pxl, MTOK, D_MODEL);
    make_map(enc, &Mwxh, pwxh, HIDDEN, D_MODEL);
    make_map(enc, &Mwxl, pwxl, HIDDEN, D_MODEL);
    make_map(enc, &Mwgh, pwgh, HIDDEN, D_MODEL);
    make_map(enc, &Mwdh, pwdh, HIDDEN, D_MODEL);
    make_map(enc, &Mwoh, pwoh, D_MODEL, HIDDEN);
    make_map(enc, &Mwol, pwol, D_MODEL, HIDDEN);
    make_map(enc, &Myh, pyh, MTOK, HIDDEN);
    make_map(enc, &Myl, pyl, MTOK, HIDDEN);

    cudaFuncSetAttribute(gemm_u, cudaFuncAttributeMaxDynamicSharedMemorySize, SMEM_U);
    cudaFuncSetAttribute(gemm_gate, cudaFuncAttributeMaxDynamicSharedMemorySize, SMEM_GATE);
    cudaFuncSetAttribute(gemm_out, cudaFuncAttributeMaxDynamicSharedMemorySize, SMEM_OUT);
    cudaFuncSetAttribute(gemm_dt, cudaFuncAttributeMaxDynamicSharedMemorySize, SMEM_DT);

    cudaStream_t s1, s2;
    cudaStreamCreateWithFlags(&s1, cudaStreamNonBlocking);
    cudaStreamCreateWithFlags(&s2, cudaStreamNonBlocking);
    cudaEvent_t eS, eG, eD;
    cudaEventCreateWithFlags(&eS, cudaEventDisableTiming);
    cudaEventCreateWithFlags(&eG, cudaEventDisableTiming);
    cudaEventCreateWithFlags(&eD, cudaEventDisableTiming);

    // splits (serial on main, like R9)
    {
        int n4 = MTOK * D_MODEL / 4;
        split_kernel<<<(n4 + 255) / 256, 256>>>((const float4*)x,
                                                (__nv_bfloat162*)pxh,
                                                (__nv_bfloat162*)pxl, n4);
        split_w_kernel<<<(4 * WN4) / 256, 256>>>((const float4*)W_x,
                                                 (const float4*)W_g,
                                                 (const float4*)W_dt,
                                                 (const float4*)W_out);
    }
    cudaEventRecord(eS, 0);

    dim3 gridH(HIDDEN / BN, MTOK / BM);    // (16, 32)
    dim3 gridD(D_MODEL / BN, MTOK / BM);   // (8, 32)

    // fork: u on main, gate on s1, dt+disc on s2 — all concurrent
    cudaStreamWaitEvent(s1, eS, 0);
    cudaStreamWaitEvent(s2, eS, 0);

    gemm_u<<<gridH, 256, SMEM_U>>>(Mxh, Mxl, Mwxh, Mwxl, b_x, pu);

    gemm_gate<<<gridH, 256, SMEM_GATE, s1>>>(Mxh, Mxl, Mwgh, b_g, pg);
    cudaEventRecord(eG, s1);

    gemm_dt<<<gridH, 256, SMEM_DT, s2>>>(Mxh, Mwdh, b_dt, pdt);
    disc_kernel<<<(HIDDEN * D_STATE + 255) / 256, 256, 0, s2>>>(A_raw, B_ssm);
    cudaEventRecord(eD, s2);

    // join: scan needs u (main), gate (s1), Ad/Bd (s2)
    cudaStreamWaitEvent(0, eG, 0);
    cudaStreamWaitEvent(0, eD, 0);

    scan1_kernel<<<(BATCH * NCHK * HIDDEN) / 128, 128>>>(C_ssm, conv_w, conv_b);
    scan2_kernel<<<(BATCH * HIDDEN * D_STATE) / 256, 256>>>();
    scan3_kernel<<<(BATCH * NCHK * HIDDEN) / 128, 128>>>(C_ssm);

    gemm_out<<<gridD, 256, SMEM_OUT>>>(Myh, Myl, Mwoh, Mwol, b_out, pout);

    ln_kernel<<<MTOK, 256>>>(x, ln_g, ln_b, out);

    cudaEventDestroy(eS);
    cudaEventDestroy(eG);
    cudaEventDestroy(eD);
    cudaStreamDestroy(s1);
    cudaStreamDestroy(s2);
}

// round 15
// speedup vs baseline: 1.0545x; 1.0105x over previous
#include <cuda_runtime.h>
#include <cuda_bf16.h>
#include <cuda.h>
#include <dlfcn.h>
#include <cstdint>

#define D_MODEL 1024
#define HIDDEN  2048
#define D_STATE 16
#define BATCH   2
#define SEQ     2048
#define MTOK    4096
#define NCHK    16
#define CHK     128

// ---------------- GEMM tiling -------------------------------------------------
#define BM 128
#define BN 128
#define BKE 64
#define RB 128
#define TILE_B (128 * 128)
#define SMEM_U    (2 * 4 * TILE_B + 1024)   // 132096: u GEMM, NS=2, 4 tiles
#define SMEM_GATE (2 * 3 * TILE_B + 1024)   // 99328 : gate GEMM, NS=2, 3 tiles
#define SMEM_OUTA (2 * 3 * TILE_B + 1024)   // 99328 : out_a, NS=2, 3 tiles
#define SMEM_OUTB (3 * 2 * TILE_B + 1024)   // 99328 : out_b, NS=3, 2 tiles
#define SMEM_DT   (3 * 2 * TILE_B + 1024)   // 99328 : dt GEMM, NS=3, 2 tiles

// ---------------- scratch ----------------------------------------------------
__device__ float g_u[(size_t)MTOK * HIDDEN];
__device__ float g_g[(size_t)MTOK * HIDDEN];
__device__ float g_outp[(size_t)MTOK * D_MODEL];
__device__ float g_outp2[(size_t)MTOK * D_MODEL];
__device__ float g_dtpart[(MTOK / BM) * HIDDEN];
__device__ float g_Ad[HIDDEN * D_STATE];
__device__ float g_Bd[HIDDEN * D_STATE];
__device__ float g_state[(size_t)BATCH * NCHK * HIDDEN * D_STATE];
__device__ float g_init[(size_t)BATCH * NCHK * HIDDEN * D_STATE];

__device__ __nv_bfloat16 g_xhi[(size_t)MTOK * D_MODEL];
__device__ __nv_bfloat16 g_xlo[(size_t)MTOK * D_MODEL];
__device__ __nv_bfloat16 g_wxhi[HIDDEN * D_MODEL];
__device__ __nv_bfloat16 g_wxlo[HIDDEN * D_MODEL];
__device__ __nv_bfloat16 g_wghi[HIDDEN * D_MODEL];
__device__ __nv_bfloat16 g_wdthi[HIDDEN * D_MODEL];
__device__ __nv_bfloat16 g_wohi[D_MODEL * HIDDEN];
__device__ __nv_bfloat16 g_wolo[D_MODEL * HIDDEN];
__device__ __nv_bfloat16 g_yhi[(size_t)MTOK * HIDDEN];
__device__ __nv_bfloat16 g_ylo[(size_t)MTOK * HIDDEN];

// ---------------- helpers ----------------------------------------------------
__device__ __forceinline__ float softplusf(float x) {
    return fmaxf(x, 0.f) + log1pf(expf(-fabsf(x)));
}
__device__ __forceinline__ float sigmoidf_(float x) {
    return 1.f / (1.f + expf(-x));
}
__device__ __forceinline__ uint32_t smem_u32(const void* p) {
    uint32_t a;
    asm("{ .reg .u64 t; cvta.to.shared.u64 t, %1; cvt.u32.u64 %0, t; }"
        : "=r"(a) : "l"(p));
    return a;
}
__device__ __forceinline__ void ldm_x4(uint32_t* r, uint32_t addr) {
    asm volatile("ldmatrix.sync.aligned.m8n8.x4.shared.b16 {%0,%1,%2,%3}, [%4];"
                 : "=r"(r[0]), "=r"(r[1]), "=r"(r[2]), "=r"(r[3]) : "r"(addr));
}
__device__ __forceinline__ void mma_bf16(float* d, const uint32_t* a,
                                         const uint32_t* b) {
    asm volatile(
        "mma.sync.aligned.m16n8k16.row.col.f32.bf16.bf16.f32 "
        "{%0,%1,%2,%3}, {%4,%5,%6,%7}, {%8,%9}, {%0,%1,%2,%3};"
        : "+f"(d[0]), "+f"(d[1]), "+f"(d[2]), "+f"(d[3])
        : "r"(a[0]), "r"(a[1]), "r"(a[2]), "r"(a[3]), "r"(b[0]), "r"(b[1]));
}
__device__ __forceinline__ void mbar_init(uint32_t addr) {
    asm volatile("mbarrier.init.shared.b64 [%0], 1;" :: "r"(addr) : "memory");
}
__device__ __forceinline__ void mbar_expect(uint32_t addr, uint32_t bytes) {
    asm volatile("mbarrier.arrive.expect_tx.shared.b64 _, [%0], %1;"
                 :: "r"(addr), "r"(bytes) : "memory");
}
__device__ __forceinline__ void mbar_wait(uint32_t addr, uint32_t parity) {
    asm volatile(
        "{\n\t.reg .pred P;\n\t"
        "W_%=:\n\t"
        "mbarrier.try_wait.parity.acquire.cta.shared::cta.b64 P, [%0], %1, 0x989680;\n\t"
        "@P bra D_%=;\n\t"
        "bra W_%=;\n\t"
        "D_%=:\n\t}"
        :: "r"(addr), "r"(parity) : "memory");
}
__device__ __forceinline__ void tma2d(uint32_t smaddr, const CUtensorMap* m,
                                      int cx, int cy, uint32_t mbar) {
    asm volatile(
        "cp.async.bulk.tensor.2d.shared::cta.global.tile.mbarrier::complete_tx::bytes "
        "[%0], [%1, {%2, %3}], [%4];"
        :: "r"(smaddr), "l"(m), "r"(cx), "r"(cy), "r"(mbar) : "memory");
}

// ---------------- fp32 -> bf16 hi/lo split (x) --------------------------------
__global__ __launch_bounds__(256) void split_kernel(
    const float4* __restrict__ src, __nv_bfloat162* __restrict__ hi,
    __nv_bfloat162* __restrict__ lo, int n4)
{
    int i = blockIdx.x * blockDim.x + threadIdx.x;
    if (i >= n4) return;
    float4 v = src[i];
    __nv_bfloat16 h0 = __float2bfloat16(v.x);
    __nv_bfloat16 h1 = __float2bfloat16(v.y);
    __nv_bfloat16 h2 = __float2bfloat16(v.z);
    __nv_bfloat16 h3 = __float2bfloat16(v.w);
    hi[i * 2 + 0] = __nv_bfloat162(h0, h1);
    hi[i * 2 + 1] = __nv_bfloat162(h2, h3);
    if (lo) {
        __nv_bfloat16 l0 = __float2bfloat16(v.x - __bfloat162float(h0));
        __nv_bfloat16 l1 = __float2bfloat16(v.y - __bfloat162float(h1));
        __nv_bfloat16 l2 = __float2bfloat16(v.z - __bfloat162float(h2));
        __nv_bfloat16 l3 = __float2bfloat16(v.w - __bfloat162float(h3));
        lo[i * 2 + 0] = __nv_bfloat162(l0, l1);
        lo[i * 2 + 1] = __nv_bfloat162(l2, l3);
    }
}

// ---------------- fused weight split ------------------------------------------
#define WN4 (HIDDEN * D_MODEL / 4)   // 524288 = 2^19
__global__ __launch_bounds__(256) void split_w_kernel(
    const float4* __restrict__ wx, const float4* __restrict__ wg,
    const float4* __restrict__ wdt, const float4* __restrict__ wo)
{
    int gi = blockIdx.x * blockDim.x + threadIdx.x;
    int arr = gi >> 19;
    int i = gi & (WN4 - 1);
    const float4* src = (arr == 0) ? wx : (arr == 1) ? wg : (arr == 2) ? wdt : wo;
    __nv_bfloat162* hi = (arr == 0) ? (__nv_bfloat162*)g_wxhi
                       : (arr == 1) ? (__nv_bfloat162*)g_wghi
                       : (arr == 2) ? (__nv_bfloat162*)g_wdthi
                                    : (__nv_bfloat162*)g_wohi;
    __nv_bfloat162* lo = (arr == 0) ? (__nv_bfloat162*)g_wxlo
                       : (arr == 3) ? (__nv_bfloat162*)g_wolo : nullptr;
    float4 v = src[i];
    __nv_bfloat16 h0 = __float2bfloat16(v.x);
    __nv_bfloat16 h1 = __float2bfloat16(v.y);
    __nv_bfloat16 h2 = __float2bfloat16(v.z);
    __nv_bfloat16 h3 = __float2bfloat16(v.w);
    hi[i * 2 + 0] = __nv_bfloat162(h0, h1);
    hi[i * 2 + 1] = __nv_bfloat162(h2, h3);
    if (lo) {
        __nv_bfloat16 l0 = __float2bfloat16(v.x - __bfloat162float(h0));
        __nv_bfloat16 l1 = __float2bfloat16(v.y - __bfloat162float(h1));
        __nv_bfloat16 l2 = __float2bfloat16(v.z - __bfloat162float(h2));
        __nv_bfloat16 l3 = __float2bfloat16(v.w - __bfloat162float(h3));
        lo[i * 2 + 0] = __nv_bfloat162(l0, l1);
        lo[i * 2 + 1] = __nv_bfloat162(l2, l3);
    }
}

// ---------------- u GEMM: 3-term, NS=2, 4 tiles (128x128) ---------------------
__global__ __launch_bounds__(256, 1) void gemm_u(
    const __grid_constant__ CUtensorMap mAh, const __grid_constant__ CUtensorMap mAl,
    const __grid_constant__ CUtensorMap mBh, const __grid_constant__ CUtensorMap mBl,
    const float* __restrict__ bias, float* __restrict__ C)
{
    constexpr uint32_t STAGE = 4 * TILE_B;
    constexpr uint32_t ALOFF = 1 * TILE_B;
    constexpr uint32_t BHOFF = 2 * TILE_B;
    constexpr uint32_t BLOFF = 3 * TILE_B;
    const int N = HIDDEN, K = D_MODEL;

    extern __shared__ char smraw[];
    uint32_t sb = (smem_u32(smraw) + 1023u) & ~1023u;
    __shared__ uint64_t mbarS[2];
    uint32_t mb = smem_u32(mbarS);

    const int tid = threadIdx.x;
    const int wid = tid >> 5, lane = tid & 31;
    const int wm = wid & 1, wn = wid >> 1;
    const int am0 = blockIdx.y * BM;
    const int bn0 = blockIdx.x * BN;

    if (tid == 0) { mbar_init(mb); mbar_init(mb + 8); }
    __syncthreads();

    auto issue = [&](int s) {
        if (tid != 0) return;
        uint32_t bar = mb + (uint32_t)(s & 1) * 8;
        mbar_expect(bar, STAGE);
        uint32_t st = sb + (uint32_t)(s & 1) * STAGE;
        int kc = s * BKE;
        tma2d(st, &mAh, kc, am0, bar);
        tma2d(st + ALOFF, &mAl, kc, am0, bar);
        tma2d(st + BHOFF, &mBh, kc, bn0, bar);
        tma2d(st + BLOFF, &mBl, kc, bn0, bar);
    };
    issue(0); issue(1);

    float acc[4][4][4];
#pragma unroll
    for (int i = 0; i < 4; i++)
#pragma unroll
        for (int j = 0; j < 4; j++)
#pragma unroll
            for (int v = 0; v < 4; v++) acc[i][j][v] = 0.f;

    const int arA = wm * 64 + (lane & 15);
    const int ahalf = lane >> 4;
    const uint32_t axor = (uint32_t)(arA & 7);
    uint32_t aoff[4];
#pragma unroll
    for (int mf = 0; mf < 4; mf++) aoff[mf] = (uint32_t)(arA + mf * 16) * RB;

    const int nrB = wn * 32 + (lane & 7) + ((lane >> 4) << 3);
    const int khalf = (lane >> 3) & 1;
    const uint32_t bxor = (uint32_t)(nrB & 7);
    uint32_t boff[2];
#pragma unroll
    for (int nf = 0; nf < 2; nf++) boff[nf] = (uint32_t)(nrB + nf * 16) * RB;

    const int NCH = K / BKE;   // 16
    for (int ch = 0; ch < NCH; ch++) {
        mbar_wait(mb + (uint32_t)(ch & 1) * 8, (uint32_t)((ch >> 1) & 1));
        const uint32_t st = sb + (uint32_t)(ch & 1) * STAGE;

#pragma unroll
        for (int ks = 0; ks < 4; ks++) {
            const uint32_t asg = (((uint32_t)(ks * 2 + ahalf)) ^ axor) << 4;
            const uint32_t bsg = (((uint32_t)(ks * 2 + khalf)) ^ bxor) << 4;
            uint32_t ah[4][4], al[4][4], bh[4][2], bl[4][2];
#pragma unroll
            for (int nf = 0; nf < 2; nf++) {
                uint32_t rr[4];
                ldm_x4(rr, st + BHOFF + boff[nf] + bsg);
                bh[nf * 2 + 0][0] = rr[0]; bh[nf * 2 + 0][1] = rr[1];
                bh[nf * 2 + 1][0] = rr[2]; bh[nf * 2 + 1][1] = rr[3];
                ldm_x4(rr, st + BLOFF + boff[nf] + bsg);
                bl[nf * 2 + 0][0] = rr[0]; bl[nf * 2 + 0][1] = rr[1];
                bl[nf * 2 + 1][0] = rr[2]; bl[nf * 2 + 1][1] = rr[3];
            }
#pragma unroll
            for (int mf = 0; mf < 4; mf++) {
                ldm_x4(ah[mf], st + aoff[mf] + asg);
                ldm_x4(al[mf], st + ALOFF + aoff[mf] + asg);
            }
#pragma unroll
            for (int mf = 0; mf < 4; mf++)
#pragma unroll
                for (int nfi = 0; nfi < 4; nfi++) {
                    mma_bf16(acc[mf][nfi], ah[mf], bh[nfi]);
                    mma_bf16(acc[mf][nfi], ah[mf], bl[nfi]);
                    mma_bf16(acc[mf][nfi], al[mf], bh[nfi]);
                }
        }
        __syncthreads();
        if (ch + 2 < NCH) issue(ch + 2);
    }

#pragma unroll
    for (int mf = 0; mf < 4; mf++) {
        const int r0 = am0 + wm * 64 + mf * 16 + (lane >> 2);
#pragma unroll
        for (int h = 0; h < 2; h++) {
            const int row = r0 + h * 8;
#pragma unroll
            for (int nfi = 0; nfi < 4; nfi++) {
                const int col = bn0 + wn * 32 + nfi * 8 + (lane & 3) * 2;
                float v0 = acc[mf][nfi][h * 2 + 0] + bias[col];
                float v1 = acc[mf][nfi][h * 2 + 1] + bias[col + 1];
                *(float2*)&C[(size_t)row * N + col] = make_float2(v0, v1);
            }
        }
    }
}

// ---------------- 2-term GEMM (A-hi x Bh + A-hi x Bl  OR  A-hi/A-lo x Gh) ----
// MODE 0: raw + bias (out_a: dA2=Ah, terms Ah*Bh + Ah*Bl)
// MODE 1: sigmoid + bias (gate: terms Ah*Gh + Al*Gh; B tile single)
template <int MODE>
__global__ __launch_bounds__(256, 2) void gemm_2term(
    const __grid_constant__ CUtensorMap mA1, const __grid_constant__ CUtensorMap mA2,
    const __grid_constant__ CUtensorMap mB1, const __grid_constant__ CUtensorMap mB2,
    const float* __restrict__ bias, float* __restrict__ C, int N, int K)
{
    // tiles: T0 = A1, T1 = (MODE==1 ? A2 : B1dup slot), T2 = B
    // layout: MODE 1 (gate): [A_hi][A_lo][G_hi]; MODE 0 (out_a): [A_hi][B_hi][B_lo]
    constexpr uint32_t T1OFF = 1 * TILE_B;
    constexpr uint32_t T2OFF = 2 * TILE_B;
    constexpr uint32_t STAGE = 3 * TILE_B;

    extern __shared__ char smraw[];
    uint32_t sb = (smem_u32(smraw) + 1023u) & ~1023u;
    __shared__ uint64_t mbarS[2];
    uint32_t mb = smem_u32(mbarS);

    const int tid = threadIdx.x;
    const int wid = tid >> 5, lane = tid & 31;
    const int wm = wid & 1, wn = wid >> 1;
    const int am0 = blockIdx.y * BM;
    const int bn0 = blockIdx.x * BN;

    if (tid == 0) { mbar_init(mb); mbar_init(mb + 8); }
    __syncthreads();

    auto issue = [&](int s) {
        if (tid != 0) return;
        uint32_t bar = mb + (uint32_t)(s & 1) * 8;
        mbar_expect(bar, STAGE);
        uint32_t st = sb + (uint32_t)(s & 1) * STAGE;
        int kc = s * BKE;
        if (MODE == 1) {
            tma2d(st, &mA1, kc, am0, bar);          // A hi
            tma2d(st + T1OFF, &mA2, kc, am0, bar);  // A lo
            tma2d(st + T2OFF, &mB1, kc, bn0, bar);  // G hi
        } else {
            tma2d(st, &mA1, kc, am0, bar);          // A hi
            tma2d(st + T1OFF, &mB1, kc, bn0, bar);  // B hi
            tma2d(st + T2OFF, &mB2, kc, bn0, bar);  // B lo
        }
    };
    issue(0); issue(1);

    float acc[4][4][4];
#pragma unroll
    for (int i = 0; i < 4; i++)
#pragma unroll
        for (int j = 0; j < 4; j++)
#pragma unroll
            for (int v = 0; v < 4; v++) acc[i][j][v] = 0.f;

    const int arA = wm * 64 + (lane & 15);
    const int ahalf = lane >> 4;
    const uint32_t axor = (uint32_t)(arA & 7);
    uint32_t aoff[4];
#pragma unroll
    for (int mf = 0; mf < 4; mf++) aoff[mf] = (uint32_t)(arA + mf * 16) * RB;

    const int nrB = wn * 32 + (lane & 7) + ((lane >> 4) << 3);
    const int khalf = (lane >> 3) & 1;
    const uint32_t bxor = (uint32_t)(nrB & 7);
    uint32_t boff[2];
#pragma unroll
    for (int nf = 0; nf < 2; nf++) boff[nf] = (uint32_t)(nrB + nf * 16) * RB;

    const int NCH = K / BKE;
    for (int ch = 0; ch < NCH; ch++) {
        mbar_wait(mb + (uint32_t)(ch & 1) * 8, (uint32_t)((ch >> 1) & 1));
        const uint32_t st = sb + (uint32_t)(ch & 1) * STAGE;

#pragma unroll
        for (int ks = 0; ks < 4; ks++) {
            const uint32_t asg = (((uint32_t)(ks * 2 + ahalf)) ^ axor) << 4;
            const uint32_t bsg = (((uint32_t)(ks * 2 + khalf)) ^ bxor) << 4;
            if (MODE == 1) {
                uint32_t ah[4][4], al[4][4], gh[4][2];
#pragma unroll
                for (int nf = 0; nf < 2; nf++) {
                    uint32_t rr[4];
                    ldm_x4(rr, st + T2OFF + boff[nf] + bsg);
                    gh[nf * 2 + 0][0] = rr[0]; gh[nf * 2 + 0][1] = rr[1];
                    gh[nf * 2 + 1][0] = rr[2]; gh[nf * 2 + 1][1] = rr[3];
                }
#pragma unroll
                for (int mf = 0; mf < 4; mf++) {
                    ldm_x4(ah[mf], st + aoff[mf] + asg);
                    ldm_x4(al[mf], st + T1OFF + aoff[mf] + asg);
                }
#pragma unroll
                for (int mf = 0; mf < 4; mf++)
#pragma unroll
                    for (int nfi = 0; nfi < 4; nfi++) {
                        mma_bf16(acc[mf][nfi], ah[mf], gh[nfi]);
                        mma_bf16(acc[mf][nfi], al[mf], gh[nfi]);
                    }
            } else {
                uint32_t ah[4][4], bh[4][2], bl[4][2];
#pragma unroll
                for (int nf = 0; nf < 2; nf++) {
                    uint32_t rr[4];
                    ldm_x4(rr, st + T1OFF + boff[nf] + bsg);
                    bh[nf * 2 + 0][0] = rr[0]; bh[nf * 2 + 0][1] = rr[1];
                    bh[nf * 2 + 1][0] = rr[2]; bh[nf * 2 + 1][1] = rr[3];
                    ldm_x4(rr, st + T2OFF + boff[nf] + bsg);
                    bl[nf * 2 + 0][0] = rr[0]; bl[nf * 2 + 0][1] = rr[1];
                    bl[nf * 2 + 1][0] = rr[2]; bl[nf * 2 + 1][1] = rr[3];
                }
#pragma unroll
                for (int mf = 0; mf < 4; mf++)
                    ldm_x4(ah[mf], st + aoff[mf] + asg);
#pragma unroll
                for (int mf = 0; mf < 4; mf++)
#pragma unroll
                    for (int nfi = 0; nfi < 4; nfi++) {
                        mma_bf16(acc[mf][nfi], ah[mf], bh[nfi]);
                        mma_bf16(acc[mf][nfi], ah[mf], bl[nfi]);
                    }
            }
        }
        __syncthreads();
        if (ch + 2 < NCH) issue(ch + 2);
    }

#pragma unroll
    for (int mf = 0; mf < 4; mf++) {
        const int r0 = am0 + wm * 64 + mf * 16 + (lane >> 2);
#pragma unroll
        for (int h = 0; h < 2; h++) {
            const int row = r0 + h * 8;
#pragma unroll
            for (int nfi = 0; nfi < 4; nfi++) {
                const int col = bn0 + wn * 32 + nfi * 8 + (lane & 3) * 2;
                float v0 = acc[mf][nfi][h * 2 + 0] + bias[col];
                float v1 = acc[mf][nfi][h * 2 + 1] + bias[col + 1];
                if (MODE == 1) { v0 = sigmoidf_(v0); v1 = sigmoidf_(v1); }
                *(float2*)&C[(size_t)row * N + col] = make_float2(v0, v1);
            }
        }
    }
}

// ---------------- 1-term GEMM: A x Bh, NS=3, 2 CTAs/SM ------------------------
// MODE 0: raw store, no bias (out_b). MODE 2: softplus colsums (dt).
template <int MODE>
__global__ __launch_bounds__(256, 2) void gemm_1term(
    const __grid_constant__ CUtensorMap mA, const __grid_constant__ CUtensorMap mB,
    const float* __restrict__ bias, float* __restrict__ C,
    float* __restrict__ colsum, int N, int K)
{
    constexpr int NS = 3;
    constexpr uint32_t STAGE = 2 * TILE_B;
    constexpr uint32_t BHOFF = TILE_B;

    extern __shared__ char smraw[];
    uint32_t sb = (smem_u32(smraw) + 1023u) & ~1023u;
    __shared__ uint64_t mbarS[NS];
    uint32_t mb = smem_u32(mbarS);

    const int tid = threadIdx.x;
    const int wid = tid >> 5, lane = tid & 31;
    const int wm = wid & 1, wn = wid >> 1;
    const int am0 = blockIdx.y * BM;
    const int bn0 = blockIdx.x * BN;

    if (tid == 0) {
#pragma unroll
        for (int s = 0; s < NS; s++) mbar_init(mb + s * 8);
    }
    __syncthreads();

    auto issue = [&](int s) {
        if (tid != 0) return;
        int slot = s % NS;
        uint32_t bar = mb + (uint32_t)slot * 8;
        mbar_expect(bar, STAGE);
        uint32_t st = sb + (uint32_t)slot * STAGE;
        int kc = s * BKE;
        tma2d(st, &mA, kc, am0, bar);
        tma2d(st + BHOFF, &mB, kc, bn0, bar);
    };
    const int NCH = K / BKE;
#pragma unroll
    for (int s = 0; s < NS; s++) if (s < NCH) issue(s);

    float acc[4][4][4];
#pragma unroll
    for (int i = 0; i < 4; i++)
#pragma unroll
        for (int j = 0; j < 4; j++)
#pragma unroll
            for (int v = 0; v < 4; v++) acc[i][j][v] = 0.f;

    const int arA = wm * 64 + (lane & 15);
    const int ahalf = lane >> 4;
    const uint32_t axor = (uint32_t)(arA & 7);
    uint32_t aoff[4];
#pragma unroll
    for (int mf = 0; mf < 4; mf++) aoff[mf] = (uint32_t)(arA + mf * 16) * RB;

    const int nrB = wn * 32 + (lane & 7) + ((lane >> 4) << 3);
    const int khalf = (lane >> 3) & 1;
    const uint32_t bxor = (uint32_t)(nrB & 7);
    uint32_t boff[2];
#pragma unroll
    for (int nf = 0; nf < 2; nf++) boff[nf] = (uint32_t)(nrB + nf * 16) * RB;

    for (int ch = 0; ch < NCH; ch++) {
        int slot = ch % NS;
        mbar_wait(mb + (uint32_t)slot * 8, (uint32_t)((ch / NS) & 1));
        const uint32_t st = sb + (uint32_t)slot * STAGE;

#pragma unroll
        for (int ks = 0; ks < 4; ks++) {
            uint32_t a[4][4], bh[4][2];
            const uint32_t asg = (((uint32_t)(ks * 2 + ahalf)) ^ axor) << 4;
            const uint32_t bsg = (((uint32_t)(ks * 2 + khalf)) ^ bxor) << 4;
#pragma unroll
            for (int nf = 0; nf < 2; nf++) {
                uint32_t rr[4];
                ldm_x4(rr, st + BHOFF + boff[nf] + bsg);
                bh[nf * 2 + 0][0] = rr[0]; bh[nf * 2 + 0][1] = rr[1];
                bh[nf * 2 + 1][0] = rr[2]; bh[nf * 2 + 1][1] = rr[3];
            }
#pragma unroll
            for (int mf = 0; mf < 4; mf++) ldm_x4(a[mf], st + aoff[mf] + asg);
#pragma unroll
            for (int mf = 0; mf < 4; mf++)
#pragma unroll
                for (int nfi = 0; nfi < 4; nfi++)
                    mma_bf16(acc[mf][nfi], a[mf], bh[nfi]);
        }
        __syncthreads();
        if (ch + NS < NCH) issue(ch + NS);
    }

    if (MODE == 2) {
        float* red = (float*)smraw;
#pragma unroll
        for (int nfi = 0; nfi < 4; nfi++) {
            const int colb = bn0 + wn * 32 + nfi * 8 + (lane & 3) * 2;
            const float b0 = bias[colb], b1 = bias[colb + 1];
            float s0 = 0.f, s1 = 0.f;
#pragma unroll
            for (int mf = 0; mf < 4; mf++) {
                s0 += softplusf(acc[mf][nfi][0] + b0);
                s1 += softplusf(acc[mf][nfi][1] + b1);
                s0 += softplusf(acc[mf][nfi][2] + b0);
                s1 += softplusf(acc[mf][nfi][3] + b1);
            }
#pragma unroll
            for (int o = 4; o <= 16; o <<= 1) {
                s0 += __shfl_xor_sync(0xffffffffu, s0, o);
                s1 += __shfl_xor_sync(0xffffffffu, s1, o);
            }
            if (lane < 4) {
                int c = wn * 32 + nfi * 8 + lane * 2;
                red[wm * 128 + c] = s0;
                red[wm * 128 + c + 1] = s1;
            }
        }
        __syncthreads();
        if (tid < 128)
            colsum[(size_t)blockIdx.y * N + bn0 + tid] = red[tid] + red[128 + tid];
    } else {
#pragma unroll
        for (int mf = 0; mf < 4; mf++) {
            const int r0 = am0 + wm * 64 + mf * 16 + (lane >> 2);
#pragma unroll
            for (int h = 0; h < 2; h++) {
                const int row = r0 + h * 8;
#pragma unroll
                for (int nfi = 0; nfi < 4; nfi++) {
                    const int col = bn0 + wn * 32 + nfi * 8 + (lane & 3) * 2;
                    *(float2*)&C[(size_t)row * N + col] =
                        make_float2(acc[mf][nfi][h * 2 + 0], acc[mf][nfi][h * 2 + 1]);
                }
            }
        }
    }
}

// ---------------- dt finalize + discretization --------------------------------
__global__ void disc_kernel(const float* __restrict__ A_raw,
                            const float* __restrict__ B_ssm)
{
    int idx = blockIdx.x * blockDim.x + threadIdx.x;
    if (idx >= HIDDEN * D_STATE) return;
    int h = idx / D_STATE;
    float sum = 0.f;
#pragma unroll
    for (int p = 0; p < MTOK / BM; p++) sum += g_dtpart[p * HIDDEN + h];
    float dt = sum * (1.f / (float)MTOK);
    dt = fminf(fmaxf(dt, 1e-3f), 2.0f);
    float a = -softplusf(A_raw[idx]);
    float ad = expf(a * dt);
    float bd = (ad - 1.0f) / (a + 1e-6f) * B_ssm[idx];
    g_Ad[idx] = ad;
    g_Bd[idx] = bd;
}

// ---------------- scan pass 1: fused conv+gate + chunk-local scan -------------
__global__ __launch_bounds__(128) void scan1_kernel(
    const float* __restrict__ C_ssm, const float* __restrict__ conv_w,
    const float* __restrict__ conv_b)
{
    int idx = blockIdx.x * blockDim.x + threadIdx.x;
    int h = idx & (HIDDEN - 1);
    int bc = idx >> 11;
    int c = bc & (NCHK - 1);

    float ad[D_STATE], bd[D_STATE], cc[D_STATE], st[D_STATE];
#pragma unroll
    for (int j = 0; j < D_STATE; j++) {
        ad[j] = g_Ad[h * D_STATE + j];
        bd[j] = g_Bd[h * D_STATE + j];
        cc[j] = C_ssm[h * D_STATE + j];
        st[j] = 0.f;
    }
    const float w0 = conv_w[h * 3 + 0], w1 = conv_w[h * 3 + 1],
                w2 = conv_w[h * 3 + 2], cb = conv_b[h];

    const int b = bc >> 4;
    const int l0 = c * CHK;
    const size_t base = ((size_t)b * SEQ + l0) * HIDDEN + h;
    const float* up = g_u + base;
    float* gp = g_g + base;

    float um = (l0 > 0) ? up[-(ptrdiff_t)HIDDEN] : 0.f;
    float cu[4], cg[4];
#pragma unroll
    for (int q = 0; q < 4; q++) {
        cu[q] = up[(size_t)q * HIDDEN];
        cg[q] = gp[(size_t)q * HIDDEN];
    }

    for (int t = 0; t < CHK; t += 4) {
        float nu[4], ng[4];
#pragma unroll
        for (int q = 0; q < 4; q++) {
            int l = l0 + t + 4 + q;
            nu[q] = (l < SEQ) ? up[(size_t)(t + 4 + q) * HIDDEN] : 0.f;
            int tt = t + 4 + q;
            ng[q] = (tt < CHK) ? gp[(size_t)tt * HIDDEN] : 0.f;
        }
#pragma unroll
        for (int q = 0; q < 4; q++) {
            float u0 = cu[q];
            float upn = (q < 3) ? cu[q + 1] : nu[0];
            float hc = cb + w0 * um + w1 * u0 + w2 * upn;
            float g = cg[q];
            float uc = u0 * g + hc * (1.f - g);
            float y0 = 0.f, y1 = 0.f, y2 = 0.f, y3 = 0.f;
#pragma unroll
            for (int j = 0; j < D_STATE; j++)
                st[j] = fmaf(ad[j], st[j], bd[j] * uc);
#pragma unroll
            for (int j = 0; j < D_STATE; j += 4) {
                y0 = fmaf(st[j + 0], cc[j + 0], y0);
                y1 = fmaf(st[j + 1], cc[j + 1], y1);
                y2 = fmaf(st[j + 2], cc[j + 2], y2);
                y3 = fmaf(st[j + 3], cc[j + 3], y3);
            }
            gp[(size_t)(t + q) * HIDDEN] = (y0 + y1) + (y2 + y3);
            um = u0;
        }
#pragma unroll
        for (int q = 0; q < 4; q++) { cu[q] = nu[q]; cg[q] = ng[q]; }
    }
    float* sp = g_state + (size_t)idx * D_STATE;
#pragma unroll
    for (int j = 0; j < D_STATE; j += 4)
        *(float4*)&sp[j] = make_float4(st[j], st[j + 1], st[j + 2], st[j + 3]);
}

// ---------------- scan pass 2: chunk-state prefix -----------------------------
__global__ __launch_bounds__(256) void scan2_kernel()
{
    int idx = blockIdx.x * blockDim.x + threadIdx.x;
    int j = idx & (D_STATE - 1);
    int h = (idx >> 4) & (HIDDEN - 1);
    int b = idx >> 15;

    float ad = g_Ad[h * D_STATE + j];
    float af = ad;
#pragma unroll
    for (int i = 0; i < 7; i++) af = af * af;

    float carry = 0.f;
#pragma unroll
    for (int c = 0; c < NCHK; c++) {
        size_t off = (((size_t)b * NCHK + c) * HIDDEN + h) * D_STATE + j;
        g_init[off] = carry;
        carry = fmaf(af, carry, g_state[off]);
    }
}

// ---------------- scan pass 3: fixup + bf16 split -----------------------------
__global__ __launch_bounds__(128) void scan3_kernel(const float* __restrict__ C_ssm)
{
    int idx = blockIdx.x * blockDim.x + threadIdx.x;
    int h = idx & (HIDDEN - 1);
    int bc = idx >> 11;
    int c = bc & (NCHK - 1);
    int b = bc >> 4;

    const size_t base = ((size_t)b * SEQ + (size_t)c * CHK) * HIDDEN + h;
    const float* yp = g_g + base;
    __nv_bfloat16* yh = g_yhi + base;
    __nv_bfloat16* yl = g_ylo + base;

    if (c == 0) {
        for (int t = 0; t < CHK; t++) {
            float yv = yp[(size_t)t * HIDDEN];
            __nv_bfloat16 hi = __float2bfloat16(yv);
            __nv_bfloat16 lo = __float2bfloat16(yv - __bfloat162float(hi));
            yh[(size_t)t * HIDDEN] = hi;
            yl[(size_t)t * HIDDEN] = lo;
        }
        return;
    }

    float ad[D_STATE], cc[D_STATE], p[D_STATE];
    const float* ip = g_init + (size_t)idx * D_STATE;
#pragma unroll
    for (int j = 0; j < D_STATE; j++) {
        ad[j] = g_Ad[h * D_STATE + j];
        cc[j] = C_ssm[h * D_STATE + j];
        p[j] = ip[j];
    }
    for (int t = 0; t < CHK; t++) {
        float y0 = 0.f, y1 = 0.f, y2 = 0.f, y3 = 0.f;
#pragma unroll
        for (int j = 0; j < D_STATE; j++) p[j] *= ad[j];
#pragma unroll
        for (int j = 0; j < D_STATE; j += 4) {
            y0 = fmaf(p[j + 0], cc[j + 0], y0);
            y1 = fmaf(p[j + 1], cc[j + 1], y1);
            y2 = fmaf(p[j + 2], cc[j + 2], y2);
            y3 = fmaf(p[j + 3], cc[j + 3], y3);
        }
        float yv = yp[(size_t)t * HIDDEN] + ((y0 + y1) + (y2 + y3));
        __nv_bfloat16 hi = __float2bfloat16(yv);
        __nv_bfloat16 lo = __float2bfloat16(yv - __bfloat162float(hi));
        yh[(size_t)t * HIDDEN] = hi;
        yl[(size_t)t * HIDDEN] = lo;
    }
}

// ---------------- residual + layernorm (sums outp + outp2) --------------------
__global__ __launch_bounds__(256) void ln_kernel(
    const float* __restrict__ x, const float* __restrict__ lng,
    const float* __restrict__ lnb, float* __restrict__ out)
{
    int row = blockIdx.x;
    __shared__ float sh[D_MODEL];
    __shared__ float rs[20];
    const float* xr = x + (size_t)row * D_MODEL;
    const float* o1 = g_outp + (size_t)row * D_MODEL;
    const float* o2 = g_outp2 + (size_t)row * D_MODEL;
    int tid = threadIdx.x;

    float s = 0.f, sq = 0.f;
    for (int i = tid; i < D_MODEL; i += 256) {
        float r = xr[i] + o1[i] + o2[i];
        sh[i] = r;
        s += r;
        sq += r * r;
    }
#pragma unroll
    for (int o = 16; o > 0; o >>= 1) {
        s += __shfl_xor_sync(0xffffffffu, s, o);
        sq += __shfl_xor_sync(0xffffffffu, sq, o);
    }
    int w = tid >> 5, ln = tid & 31;
    if (ln == 0) { rs[w] = s; rs[8 + w] = sq; }
    __syncthreads();
    if (tid == 0) {
        float ts = 0.f, tq = 0.f;
#pragma unroll
        for (int i = 0; i < 8; i++) { ts += rs[i]; tq += rs[8 + i]; }
        float mean = ts * (1.f / (float)D_MODEL);
        float var = tq * (1.f / (float)D_MODEL) - mean * mean;
        rs[16] = mean;
        rs[17] = rsqrtf(var + 1e-5f);
    }
    __syncthreads();
    float mean = rs[16], inv = rs[17];
    for (int i = tid; i < D_MODEL; i += 256)
        out[(size_t)row * D_MODEL + i] = (sh[i] - mean) * inv * lng[i] + lnb[i];
}

// ---------------- host: tensormap encode via dlopen ---------------------------
typedef CUresult (*PFN_encode)(CUtensorMap*, CUtensorMapDataType, cuuint32_t, void*,
    const cuuint64_t*, const cuuint64_t*, const cuuint32_t*, const cuuint32_t*,
    CUtensorMapInterleave, CUtensorMapSwizzle, CUtensorMapL2promotion,
    CUtensorMapFloatOOBfill);

static void make_map(PFN_encode enc, CUtensorMap* m, void* ptr, int rows, int K)
{
    cuuint64_t dims[2] = {(cuuint64_t)K, (cuuint64_t)rows};
    cuuint64_t strides[1] = {(cuuint64_t)K * 2};
    cuuint32_t box[2] = {64u, 128u};
    cuuint32_t es[2] = {1u, 1u};
    enc(m, CU_TENSOR_MAP_DATA_TYPE_BFLOAT16, 2, ptr, dims, strides, box, es,
        CU_TENSOR_MAP_INTERLEAVE_NONE, CU_TENSOR_MAP_SWIZZLE_128B,
        CU_TENSOR_MAP_L2_PROMOTION_L2_128B, CU_TENSOR_MAP_FLOAT_OOB_FILL_NONE);
}

// ---------------- launch -----------------------------------------------------
extern "C" void kernel_launch(void* const* d_in, const int* in_sizes, int n_in,
                              void* d_out, int out_size)
{
    const float* x      = (const float*)d_in[0];
    const float* W_x    = (const float*)d_in[1];
    const float* b_x    = (const float*)d_in[2];
    const float* W_g    = (const float*)d_in[3];
    const float* b_g    = (const float*)d_in[4];
    const float* conv_w = (const float*)d_in[5];
    const float* conv_b = (const float*)d_in[6];
    const float* A_raw  = (const float*)d_in[7];
    const float* B_ssm  = (const float*)d_in[8];
    const float* C_ssm  = (const float*)d_in[9];
    const float* W_dt   = (const float*)d_in[10];
    const float* b_dt   = (const float*)d_in[11];
    const float* W_out  = (const float*)d_in[12];
    const float* b_out  = (const float*)d_in[13];
    const float* ln_g   = (const float*)d_in[14];
    const float* ln_b   = (const float*)d_in[15];
    float* out = (float*)d_out;

    float *pu, *pg, *pdt, *pout, *pout2;
    __nv_bfloat16 *pxh, *pxl, *pwxh, *pwxl, *pwgh, *pwdh, *pwoh, *pwol, *pyh, *pyl;
    cudaGetSymbolAddress((void**)&pu, g_u);
    cudaGetSymbolAddress((void**)&pg, g_g);
    cudaGetSymbolAddress((void**)&pdt, g_dtpart);
    cudaGetSymbolAddress((void**)&pout, g_outp);
    cudaGetSymbolAddress((void**)&pout2, g_outp2);
    cudaGetSymbolAddress((void**)&pxh, g_xhi);
    cudaGetSymbolAddress((void**)&pxl, g_xlo);
    cudaGetSymbolAddress((void**)&pwxh, g_wxhi);
    cudaGetSymbolAddress((void**)&pwxl, g_wxlo);
    cudaGetSymbolAddress((void**)&pwgh, g_wghi);
    cudaGetSymbolAddress((void**)&pwdh, g_wdthi);
    cudaGetSymbolAddress((void**)&pwoh, g_wohi);
    cudaGetSymbolAddress((void**)&pwol, g_wolo);
    cudaGetSymbolAddress((void**)&pyh, g_yhi);
    cudaGetSymbolAddress((void**)&pyl, g_ylo);

    void* dl = dlopen("libcuda.so.1", RTLD_NOW);
    if (!dl) dl = dlopen("libcuda.so", RTLD_NOW);
    PFN_encode enc = dl ? (PFN_encode)dlsym(dl, "cuTensorMapEncodeTiled") : nullptr;

    CUtensorMap Mxh, Mxl, Mwxh, Mwxl, Mwgh, Mwdh, Mwoh, Mwol, Myh, Myl;
    make_map(enc, &Mxh, pxh, MTOK, D_MODEL);
    make_map(enc, &Mxl, pxl, MTOK, D_MODEL);
    make_map(enc, &Mwxh, pwxh, HIDDEN, D_MODEL);
    make_map(enc, &Mwxl, pwxl, HIDDEN, D_MODEL);
    make_map(enc, &Mwgh, pwgh, HIDDEN, D_MODEL);
    make_map(enc, &Mwdh, pwdh, HIDDEN, D_MODEL);
    make_map(enc, &Mwoh, pwoh, D_MODEL, HIDDEN);
    make_map(enc, &Mwol, pwol, D_MODEL, HIDDEN);
    make_map(enc, &Myh, pyh, MTOK, HIDDEN);
    make_map(enc, &Myl, pyl, MTOK, HIDDEN);

    cudaFuncSetAttribute(gemm_u, cudaFuncAttributeMaxDynamicSharedMemorySize, SMEM_U);
    cudaFuncSetAttribute(gemm_2term<0>, cudaFuncAttributeMaxDynamicSharedMemorySize, SMEM_OUTA);
    cudaFuncSetAttribute(gemm_2term<1>, cudaFuncAttributeMaxDynamicSharedMemorySize, SMEM_GATE);
    cudaFuncSetAttribute(gemm_1term<0>, cudaFuncAttributeMaxDynamicSharedMemorySize, SMEM_OUTB);
    cudaFuncSetAttribute(gemm_1term<2>, cudaFuncAttributeMaxDynamicSharedMemorySize, SMEM_DT);

    cudaStream_t s1, s2;
    cudaStreamCreateWithFlags(&s1, cudaStreamNonBlocking);
    cudaStreamCreateWithFlags(&s2, cudaStreamNonBlocking);
    cudaEvent_t eS, eG, eD, eY, eO;
    cudaEventCreateWithFlags(&eS, cudaEventDisableTiming);
    cudaEventCreateWithFlags(&eG, cudaEventDisableTiming);
    cudaEventCreateWithFlags(&eD, cudaEventDisableTiming);
    cudaEventCreateWithFlags(&eY, cudaEventDisableTiming);
    cudaEventCreateWithFlags(&eO, cudaEventDisableTiming);

    // splits (serial on main)
    {
        int n4 = MTOK * D_MODEL / 4;
        split_kernel<<<(n4 + 255) / 256, 256>>>((const float4*)x,
                                                (__nv_bfloat162*)pxh,
                                                (__nv_bfloat162*)pxl, n4);
        split_w_kernel<<<(4 * WN4) / 256, 256>>>((const float4*)W_x,
                                                 (const float4*)W_g,
                                                 (const float4*)W_dt,
                                                 (const float4*)W_out);
    }
    cudaEventRecord(eS, 0);

    dim3 gridH(HIDDEN / BN, MTOK / BM);    // (16, 32)
    dim3 gridD(D_MODEL / BN, MTOK / BM);   // (8, 32)

    // phase 1: u (main) || gate (s1) || dt+disc (s2)
    cudaStreamWaitEvent(s1, eS, 0);
    cudaStreamWaitEvent(s2, eS, 0);

    gemm_u<<<gridH, 256, SMEM_U>>>(Mxh, Mxl, Mwxh, Mwxl, b_x, pu);

    gemm_2term<1><<<gridH, 256, SMEM_GATE, s1>>>(Mxh, Mxl, Mwgh, Mwgh,
                                                 b_g, pg, HIDDEN, D_MODEL);
    cudaEventRecord(eG, s1);

    gemm_1term<2><<<gridH, 256, SMEM_DT, s2>>>(Mxh, Mwdh, b_dt, nullptr, pdt,
                                               HIDDEN, D_MODEL);
    disc_kernel<<<(HIDDEN * D_STATE + 255) / 256, 256, 0, s2>>>(A_raw, B_ssm);
    cudaEventRecord(eD, s2);

    cudaStreamWaitEvent(0, eG, 0);
    cudaStreamWaitEvent(0, eD, 0);

    scan1_kernel<<<(BATCH * NCHK * HIDDEN) / 128, 128>>>(C_ssm, conv_w, conv_b);
    scan2_kernel<<<(BATCH * HIDDEN * D_STATE) / 256, 256>>>();
    scan3_kernel<<<(BATCH * NCHK * HIDDEN) / 128, 128>>>(C_ssm);
    cudaEventRecord(eY, 0);

    // phase 2: out_a (main) || out_b (s1)
    cudaStreamWaitEvent(s1, eY, 0);
    gemm_2term<0><<<gridD, 256, SMEM_OUTA>>>(Myh, Myh, Mwoh, Mwol,
                                             b_out, pout, D_MODEL, HIDDEN);
    gemm_1term<0><<<gridD, 256, SMEM_OUTB, s1>>>(Myl, Mwoh, nullptr, pout2,
                                                 nullptr, D_MODEL, HIDDEN);
    cudaEventRecord(eO, s1);
    cudaStreamWaitEvent(0, eO, 0);

    ln_kernel<<<MTOK, 256>>>(x, ln_g, ln_b, out);

    cudaEventDestroy(eS);
    cudaEventDestroy(eG);
    cudaEventDestroy(eD);
    cudaEventDestroy(eY);
    cudaEventDestroy(eO);
    cudaStreamDestroy(s1);
    cudaStreamDestroy(s2);
}